// round 2
// baseline (speedup 1.0000x reference)
#include <cuda_runtime.h>
#include <math.h>
#include <stdint.h>

#define BB 4
#define SS 1024
#define DD 1024
#define HH 16
#define HDIM 64
#define FFD 4096
#define NROWS (BB*SS)   // 4096

// ---------------- scratch (static device globals; allocation-free) -------------
__device__ float g_H1[NROWS*DD];    // LN outputs (reused for LN2)
__device__ float g_Q [NROWS*DD];
__device__ float g_K [NROWS*DD];
__device__ float g_V [NROWS*DD];
__device__ float g_ATT[NROWS*DD];
__device__ float g_X1[NROWS*DD];
__device__ float g_G [NROWS*FFD];   // gelu(h2@w1)
__device__ float g_bias[NROWS];     // per (b,s) attention key bias: -1e30 or 0
__device__ int   g_mask_mode;       // 0=int32, 1=byte/bool, 2=float32

// ---------------- mask dtype sniffing -----------------------------------------
// Reference mask is jax bool; harness may deliver it as int32 / uint8 / float32.
// Scan the first B*S bytes (safe under every interpretation) and classify by
// which byte-residues (mod 4) carry nonzero values.
__global__ void mask_detect_kernel(const unsigned char* __restrict__ m) {
    __shared__ int f1, f23;
    if (threadIdx.x == 0) { f1 = 0; f23 = 0; }
    __syncthreads();
    int l1 = 0, l23 = 0;
    for (int i = threadIdx.x; i < NROWS; i += 256) {
        if (m[i]) {
            const int r = i & 3;
            if (r == 1) l1 = 1;
            else if (r >= 2) l23 = 1;
        }
    }
    if (l1)  atomicOr(&f1, 1);
    if (l23) atomicOr(&f23, 1);
    __syncthreads();
    if (threadIdx.x == 0)
        g_mask_mode = f1 ? 1 : (f23 ? 2 : 0);
}

__global__ void mask_convert_kernel(const void* __restrict__ m) {
    const int i = blockIdx.x * blockDim.x + threadIdx.x;
    if (i >= NROWS) return;
    const int mode = g_mask_mode;
    bool t;
    if (mode == 1)      t = ((const unsigned char*)m)[i] != 0;
    else if (mode == 2) t = ((const float*)m)[i] != 0.0f;
    else                t = ((const int*)m)[i] != 0;
    g_bias[i] = t ? -1e30f : 0.0f;
}

// ---------------- LayerNorm: one block per row, 256 threads -------------------
__global__ void ln_kernel(const float* __restrict__ x, const float* __restrict__ w,
                          const float* __restrict__ b, float* __restrict__ out) {
    const int row = blockIdx.x;
    const int t = threadIdx.x;
    const float4* xr = (const float4*)(x + (size_t)row * DD);
    float4 xv = xr[t];
    float s  = xv.x + xv.y + xv.z + xv.w;
    float s2 = xv.x*xv.x + xv.y*xv.y + xv.z*xv.z + xv.w*xv.w;
    #pragma unroll
    for (int m = 16; m; m >>= 1) {
        s  += __shfl_xor_sync(0xffffffffu, s,  m);
        s2 += __shfl_xor_sync(0xffffffffu, s2, m);
    }
    __shared__ float ss[8], ss2[8];
    if ((t & 31) == 0) { ss[t >> 5] = s; ss2[t >> 5] = s2; }
    __syncthreads();
    s = 0.f; s2 = 0.f;
    #pragma unroll
    for (int i = 0; i < 8; i++) { s += ss[i]; s2 += ss2[i]; }
    const float mean = s * (1.0f / DD);
    const float var  = s2 * (1.0f / DD) - mean * mean;
    const float inv  = rsqrtf(var + 1e-5f);
    float4 wv = ((const float4*)w)[t];
    float4 bv = ((const float4*)b)[t];
    float4 o;
    o.x = (xv.x - mean) * inv * wv.x + bv.x;
    o.y = (xv.y - mean) * inv * wv.y + bv.y;
    o.z = (xv.z - mean) * inv * wv.z + bv.z;
    o.w = (xv.w - mean) * inv * wv.w + bv.w;
    ((float4*)(out + (size_t)row * DD))[t] = o;
}

// ---------------- RoPE on Q and K in-place --------------------------------------
__global__ void rope_kernel(float* __restrict__ Q, float* __restrict__ K,
                            const float* __restrict__ cosT, const float* __restrict__ sinT) {
    const int idx = blockIdx.x * blockDim.x + threadIdx.x;   // B*S*H*32 = 2097152
    const int p = idx & 31;
    const int h = (idx >> 5) & 15;
    const int s = (idx >> 9) & 1023;
    const int b = idx >> 19;
    const float c  = cosT[s * 32 + p];
    const float sn = sinT[s * 32 + p];
    const size_t base = ((size_t)(b * SS + s)) * DD + h * HDIM + 2 * p;
    float2 q = *(float2*)(Q + base);
    float2 k = *(float2*)(K + base);
    float2 qo, ko;
    qo.x = q.x * c - q.y * sn;  qo.y = q.x * sn + q.y * c;
    ko.x = k.x * c - k.y * sn;  ko.y = k.x * sn + k.y * c;
    *(float2*)(Q + base) = qo;
    *(float2*)(K + base) = ko;
}

// ---------------- SGEMM 128x128x8, 256 threads, 8x8 microtile -------------------
// C[M,N] = epilogue(A[M,K] @ B[K,N])   EPI: 0=none, 1=+Res, 2=exact gelu
template<int EPI>
__global__ void __launch_bounds__(256, 2)
gemm_kernel(const float* __restrict__ A, const float* __restrict__ Bm,
            const float* __restrict__ Res, float* __restrict__ C,
            int M, int N, int K) {
    __shared__ float As[8][128];   // transposed: As[k][m]
    __shared__ float Bs[8][128];
    const int tid = threadIdx.x;
    const int tx = tid & 15, ty = tid >> 4;
    const int bx = blockIdx.x, by = blockIdx.y;

    const float* Ab = A + (size_t)(by * 128) * K;
    const float* Bb = Bm + bx * 128;

    const int arow = tid >> 1, ak = (tid & 1) * 4;
    const int brow = tid >> 5, bcol = (tid & 31) * 4;

    float acc[8][8];
    #pragma unroll
    for (int i = 0; i < 8; i++)
        #pragma unroll
        for (int j = 0; j < 8; j++) acc[i][j] = 0.f;

    float4 av = *(const float4*)(Ab + (size_t)arow * K + ak);
    float4 bv = *(const float4*)(Bb + (size_t)brow * N + bcol);

    for (int k0 = 0; k0 < K; k0 += 8) {
        As[ak + 0][arow] = av.x;
        As[ak + 1][arow] = av.y;
        As[ak + 2][arow] = av.z;
        As[ak + 3][arow] = av.w;
        *(float4*)(&Bs[brow][bcol]) = bv;
        __syncthreads();

        if (k0 + 8 < K) {
            av = *(const float4*)(Ab + (size_t)arow * K + k0 + 8 + ak);
            bv = *(const float4*)(Bb + (size_t)(k0 + 8 + brow) * N + bcol);
        }

        #pragma unroll
        for (int k = 0; k < 8; k++) {
            float a[8], bb2[8];
            *(float4*)(a)     = *(float4*)(&As[k][ty * 8]);
            *(float4*)(a + 4) = *(float4*)(&As[k][ty * 8 + 4]);
            *(float4*)(bb2)     = *(float4*)(&Bs[k][tx * 8]);
            *(float4*)(bb2 + 4) = *(float4*)(&Bs[k][tx * 8 + 4]);
            #pragma unroll
            for (int i = 0; i < 8; i++)
                #pragma unroll
                for (int j = 0; j < 8; j++)
                    acc[i][j] = fmaf(a[i], bb2[j], acc[i][j]);
        }
        __syncthreads();
    }

    #pragma unroll
    for (int i = 0; i < 8; i++) {
        const size_t row = (size_t)(by * 128 + ty * 8 + i);
        float* cp = C + row * N + bx * 128 + tx * 8;
        float v[8];
        #pragma unroll
        for (int j = 0; j < 8; j++) v[j] = acc[i][j];
        if (EPI == 1) {
            const float* rp = Res + row * N + bx * 128 + tx * 8;
            float4 r0 = *(const float4*)(rp);
            float4 r1 = *(const float4*)(rp + 4);
            v[0] += r0.x; v[1] += r0.y; v[2] += r0.z; v[3] += r0.w;
            v[4] += r1.x; v[5] += r1.y; v[6] += r1.z; v[7] += r1.w;
        }
        if (EPI == 2) {
            #pragma unroll
            for (int j = 0; j < 8; j++)
                v[j] = 0.5f * v[j] * (1.0f + erff(v[j] * 0.70710678118654752f));
        }
        float4 o0 = {v[0], v[1], v[2], v[3]};
        float4 o1 = {v[4], v[5], v[6], v[7]};
        *(float4*)(cp)     = o0;
        *(float4*)(cp + 4) = o1;
    }
}

// ---------------- Flash attention: block = (b, h, 64-query tile) ----------------
// 256 threads: tx = tid&15 (key/dim cols), ty = tid>>4 (query rows), 4x4 microtile
#define PADW 68
__global__ void __launch_bounds__(256, 2)
attn_kernel(const float* __restrict__ Qg, const float* __restrict__ Kg,
            const float* __restrict__ Vg, const float* __restrict__ biasg,
            float* __restrict__ Og) {
    extern __shared__ float sm[];
    float* QsT = sm;                 // [64 d][PADW rows]
    float* KP  = sm + 64 * PADW;     // KsT[d][col] then PsT[col][row]
    float* Vs  = sm + 2 * 64 * PADW; // [64 key][PADW dims]

    const int tid = threadIdx.x;
    const int tx = tid & 15, ty = tid >> 4;
    const int qt = blockIdx.x, h = blockIdx.y, b = blockIdx.z;
    const int row0 = qt * 64;

    // load Q tile transposed: QsT[d][r]
    {
        const int r = tid >> 2;
        const int g = (tid & 3) * 16;
        const float* qp = Qg + ((size_t)(b * SS + row0 + r)) * DD + h * HDIM + g;
        #pragma unroll
        for (int ii = 0; ii < 4; ii++) {
            float4 v = *(const float4*)(qp + ii * 4);
            const int d = g + ii * 4;
            QsT[(d + 0) * PADW + r] = v.x;
            QsT[(d + 1) * PADW + r] = v.y;
            QsT[(d + 2) * PADW + r] = v.z;
            QsT[(d + 3) * PADW + r] = v.w;
        }
    }

    float m_i[4], l_i[4], o_acc[4][4];
    #pragma unroll
    for (int i = 0; i < 4; i++) {
        m_i[i] = -1e30f; l_i[i] = 0.f;
        #pragma unroll
        for (int j = 0; j < 4; j++) o_acc[i][j] = 0.f;
    }
    const float* biasb = biasg + b * SS;

    for (int kt = 0; kt < 16; kt++) {
        __syncthreads();   // previous iter's P/V reads done before overwrite
        {
            const int r = tid >> 2;
            const int g = (tid & 3) * 16;
            const float* kp = Kg + ((size_t)(b * SS + kt * 64 + r)) * DD + h * HDIM + g;
            #pragma unroll
            for (int ii = 0; ii < 4; ii++) {
                float4 v = *(const float4*)(kp + ii * 4);
                const int d = g + ii * 4;
                KP[(d + 0) * PADW + r] = v.x;
                KP[(d + 1) * PADW + r] = v.y;
                KP[(d + 2) * PADW + r] = v.z;
                KP[(d + 3) * PADW + r] = v.w;
            }
            const float* vp = Vg + ((size_t)(b * SS + kt * 64 + r)) * DD + h * HDIM + g;
            #pragma unroll
            for (int ii = 0; ii < 4; ii++)
                *(float4*)(&Vs[r * PADW + g + ii * 4]) = *(const float4*)(vp + ii * 4);
        }
        __syncthreads();

        // S microtile
        float s[4][4];
        #pragma unroll
        for (int i = 0; i < 4; i++)
            #pragma unroll
            for (int j = 0; j < 4; j++) s[i][j] = 0.f;
        #pragma unroll 8
        for (int d = 0; d < 64; d++) {
            float4 a  = *(float4*)(&QsT[d * PADW + ty * 4]);
            float4 kb = *(float4*)(&KP [d * PADW + tx * 4]);
            const float ar[4] = {a.x, a.y, a.z, a.w};
            const float kr[4] = {kb.x, kb.y, kb.z, kb.w};
            #pragma unroll
            for (int i = 0; i < 4; i++)
                #pragma unroll
                for (int j = 0; j < 4; j++)
                    s[i][j] = fmaf(ar[i], kr[j], s[i][j]);
        }
        // scale + mask bias
        const float4 bk = *(const float4*)(biasb + kt * 64 + tx * 4);
        const float bias[4] = {bk.x, bk.y, bk.z, bk.w};
        #pragma unroll
        for (int i = 0; i < 4; i++)
            #pragma unroll
            for (int j = 0; j < 4; j++)
                s[i][j] = s[i][j] * 0.125f + bias[j];

        // online softmax per row
        #pragma unroll
        for (int i = 0; i < 4; i++) {
            float mt = fmaxf(fmaxf(s[i][0], s[i][1]), fmaxf(s[i][2], s[i][3]));
            mt = fmaxf(mt, __shfl_xor_sync(0xffffffffu, mt, 1));
            mt = fmaxf(mt, __shfl_xor_sync(0xffffffffu, mt, 2));
            mt = fmaxf(mt, __shfl_xor_sync(0xffffffffu, mt, 4));
            mt = fmaxf(mt, __shfl_xor_sync(0xffffffffu, mt, 8));
            const float mn = fmaxf(m_i[i], mt);
            const float corr = __expf(m_i[i] - mn);
            m_i[i] = mn;
            l_i[i] *= corr;
            #pragma unroll
            for (int j = 0; j < 4; j++) o_acc[i][j] *= corr;
            float ps = 0.f;
            #pragma unroll
            for (int j = 0; j < 4; j++) { s[i][j] = __expf(s[i][j] - mn); ps += s[i][j]; }
            ps += __shfl_xor_sync(0xffffffffu, ps, 1);
            ps += __shfl_xor_sync(0xffffffffu, ps, 2);
            ps += __shfl_xor_sync(0xffffffffu, ps, 4);
            ps += __shfl_xor_sync(0xffffffffu, ps, 8);
            l_i[i] += ps;
        }

        __syncthreads();   // all KsT reads done before P overwrite
        #pragma unroll
        for (int i = 0; i < 4; i++)
            #pragma unroll
            for (int j = 0; j < 4; j++)
                KP[(tx * 4 + j) * PADW + ty * 4 + i] = s[i][j];
        __syncthreads();

        // O += P @ V
        #pragma unroll 8
        for (int kk = 0; kk < 64; kk++) {
            float4 a  = *(float4*)(&KP[kk * PADW + ty * 4]);
            float4 vv = *(float4*)(&Vs[kk * PADW + tx * 4]);
            const float ar[4] = {a.x, a.y, a.z, a.w};
            const float vr[4] = {vv.x, vv.y, vv.z, vv.w};
            #pragma unroll
            for (int i = 0; i < 4; i++)
                #pragma unroll
                for (int j = 0; j < 4; j++)
                    o_acc[i][j] = fmaf(ar[i], vr[j], o_acc[i][j]);
        }
    }

    #pragma unroll
    for (int i = 0; i < 4; i++) {
        const float inv = 1.0f / l_i[i];
        const size_t row = (size_t)(b * SS + row0 + ty * 4 + i);
        float4 o = {o_acc[i][0] * inv, o_acc[i][1] * inv, o_acc[i][2] * inv, o_acc[i][3] * inv};
        *(float4*)(Og + row * DD + h * HDIM + tx * 4) = o;
    }
}

// -------------------------------- launch ---------------------------------------
extern "C" void kernel_launch(void* const* d_in, const int* in_sizes, int n_in,
                              void* d_out, int out_size) {
    const float* x    = (const float*)d_in[0];
    const void*  mask = d_in[1];
    const float* fcos = (const float*)d_in[2];
    const float* fsin = (const float*)d_in[3];
    const float* wq   = (const float*)d_in[4];
    const float* wk   = (const float*)d_in[5];
    const float* wv   = (const float*)d_in[6];
    const float* wo   = (const float*)d_in[7];
    const float* w1   = (const float*)d_in[8];
    const float* w2   = (const float*)d_in[9];
    const float* ln1w = (const float*)d_in[10];
    const float* ln1b = (const float*)d_in[11];
    const float* ln2w = (const float*)d_in[12];
    const float* ln2b = (const float*)d_in[13];
    float* out = (float*)d_out;

    float *H1, *Q, *K, *V, *ATT, *X1, *G, *BIAS;
    cudaGetSymbolAddress((void**)&H1,   g_H1);
    cudaGetSymbolAddress((void**)&Q,    g_Q);
    cudaGetSymbolAddress((void**)&K,    g_K);
    cudaGetSymbolAddress((void**)&V,    g_V);
    cudaGetSymbolAddress((void**)&ATT,  g_ATT);
    cudaGetSymbolAddress((void**)&X1,   g_X1);
    cudaGetSymbolAddress((void**)&G,    g_G);
    cudaGetSymbolAddress((void**)&BIAS, g_bias);

    static bool attr_set = false;
    if (!attr_set) {
        cudaFuncSetAttribute(attn_kernel, cudaFuncAttributeMaxDynamicSharedMemorySize,
                             3 * 64 * PADW * (int)sizeof(float));
        attr_set = true;
    }

    // 0. mask dtype sniff + conversion to float bias
    mask_detect_kernel<<<1, 256>>>((const unsigned char*)mask);
    mask_convert_kernel<<<NROWS / 256, 256>>>(mask);
    // 1. h = LN1(x)
    ln_kernel<<<NROWS, 256>>>(x, ln1w, ln1b, H1);
    // 2. Q,K,V = h @ wq/wk/wv
    dim3 g1024(DD / 128, NROWS / 128);
    gemm_kernel<0><<<g1024, 256>>>(H1, wq, nullptr, Q, NROWS, DD, DD);
    gemm_kernel<0><<<g1024, 256>>>(H1, wk, nullptr, K, NROWS, DD, DD);
    gemm_kernel<0><<<g1024, 256>>>(H1, wv, nullptr, V, NROWS, DD, DD);
    // 3. RoPE in-place on Q, K
    rope_kernel<<<(BB * SS * HH * 32) / 256, 256>>>(Q, K, fcos, fsin);
    // 4. attention -> ATT
    attn_kernel<<<dim3(SS / 64, HH, BB), 256, 3 * 64 * PADW * sizeof(float)>>>(Q, K, V, BIAS, ATT);
    // 5. X1 = x + ATT @ wo
    gemm_kernel<1><<<g1024, 256>>>(ATT, wo, x, X1, NROWS, DD, DD);
    // 6. h2 = LN2(X1)
    ln_kernel<<<NROWS, 256>>>(X1, ln2w, ln2b, H1);
    // 7. G = gelu(h2 @ w1)
    dim3 gff(FFD / 128, NROWS / 128);
    gemm_kernel<2><<<gff, 256>>>(H1, w1, nullptr, G, NROWS, FFD, DD);
    // 8. out = X1 + G @ w2
    gemm_kernel<1><<<g1024, 256>>>(G, w2, X1, out, NROWS, DD, FFD);
}

// round 5
// speedup vs baseline: 1.8628x; 1.8628x over previous
#include <cuda_runtime.h>
#include <math.h>
#include <stdint.h>

#define BB 4
#define SS 1024
#define DD 1024
#define HH 16
#define HDIM 64
#define FFD 4096
#define NROWS (BB*SS)   // 4096
#define QKVN 3072

// ---------------- scratch (static device globals; allocation-free) -------------
__device__ float g_H1 [NROWS*DD];
__device__ float g_QKV[NROWS*QKVN];   // packed Q|K|V per row
__device__ float g_ATT[NROWS*DD];
__device__ float g_X1 [NROWS*DD];
__device__ float g_G  [NROWS*FFD];
__device__ float g_bias[NROWS];
__device__ int   g_mask_mode;
// transposed weights ([N][K], K-major rows)
__device__ float g_WQKVT[QKVN*DD];
__device__ float g_WOT[DD*DD];
__device__ float g_W1T[FFD*DD];
__device__ float g_W2T[DD*FFD];

__device__ __forceinline__ uint32_t f2tf32(float x) {
    uint32_t u; asm("cvt.rna.tf32.f32 %0, %1;" : "=r"(u) : "f"(x)); return u;
}
__device__ __forceinline__ void mma16n8k8(float* d, const uint32_t* a, const uint32_t* b) {
    asm volatile("mma.sync.aligned.m16n8k8.row.col.f32.tf32.tf32.f32 "
        "{%0,%1,%2,%3}, {%4,%5,%6,%7}, {%8,%9}, {%0,%1,%2,%3};"
        : "+f"(d[0]), "+f"(d[1]), "+f"(d[2]), "+f"(d[3])
        : "r"(a[0]), "r"(a[1]), "r"(a[2]), "r"(a[3]), "r"(b[0]), "r"(b[1]));
}

// ---------------- mask dtype sniffing -----------------------------------------
__global__ void mask_detect_kernel(const unsigned char* __restrict__ m) {
    __shared__ int f1, f23;
    if (threadIdx.x == 0) { f1 = 0; f23 = 0; }
    __syncthreads();
    int l1 = 0, l23 = 0;
    for (int i = threadIdx.x; i < NROWS; i += 256) {
        if (m[i]) {
            const int r = i & 3;
            if (r == 1) l1 = 1;
            else if (r >= 2) l23 = 1;
        }
    }
    if (l1)  atomicOr(&f1, 1);
    if (l23) atomicOr(&f23, 1);
    __syncthreads();
    if (threadIdx.x == 0)
        g_mask_mode = f1 ? 1 : (f23 ? 2 : 0);
}
__global__ void mask_convert_kernel(const void* __restrict__ m) {
    const int i = blockIdx.x * blockDim.x + threadIdx.x;
    if (i >= NROWS) return;
    const int mode = g_mask_mode;
    bool t;
    if (mode == 1)      t = ((const unsigned char*)m)[i] != 0;
    else if (mode == 2) t = ((const float*)m)[i] != 0.0f;
    else                t = ((const int*)m)[i] != 0;
    g_bias[i] = t ? -1e30f : 0.0f;
}

// ---------------- weight transpose: out[c][r] = in[r][c] ------------------------
__global__ void transpose_kernel(const float* __restrict__ in, float* __restrict__ out,
                                 int R, int Ccols) {
    __shared__ float t[32][33];
    const int c0 = blockIdx.x * 32, r0 = blockIdx.y * 32;
    const int x = threadIdx.x, y = threadIdx.y;
    #pragma unroll
    for (int i = 0; i < 32; i += 8)
        t[y + i][x] = in[(size_t)(r0 + y + i) * Ccols + c0 + x];
    __syncthreads();
    #pragma unroll
    for (int i = 0; i < 32; i += 8)
        out[(size_t)(c0 + y + i) * R + r0 + x] = t[x][y + i];
}

// ---------------- LayerNorm ----------------------------------------------------
__global__ void ln_kernel(const float* __restrict__ x, const float* __restrict__ w,
                          const float* __restrict__ b, float* __restrict__ out) {
    const int row = blockIdx.x;
    const int t = threadIdx.x;
    const float4* xr = (const float4*)(x + (size_t)row * DD);
    float4 xv = xr[t];
    float s  = xv.x + xv.y + xv.z + xv.w;
    float s2 = xv.x*xv.x + xv.y*xv.y + xv.z*xv.z + xv.w*xv.w;
    #pragma unroll
    for (int m = 16; m; m >>= 1) {
        s  += __shfl_xor_sync(0xffffffffu, s,  m);
        s2 += __shfl_xor_sync(0xffffffffu, s2, m);
    }
    __shared__ float ss[8], ss2[8];
    if ((t & 31) == 0) { ss[t >> 5] = s; ss2[t >> 5] = s2; }
    __syncthreads();
    s = 0.f; s2 = 0.f;
    #pragma unroll
    for (int i = 0; i < 8; i++) { s += ss[i]; s2 += ss2[i]; }
    const float mean = s * (1.0f / DD);
    const float var  = s2 * (1.0f / DD) - mean * mean;
    const float inv  = rsqrtf(var + 1e-5f);
    float4 wv = ((const float4*)w)[t];
    float4 bv = ((const float4*)b)[t];
    float4 o;
    o.x = (xv.x - mean) * inv * wv.x + bv.x;
    o.y = (xv.y - mean) * inv * wv.y + bv.y;
    o.z = (xv.z - mean) * inv * wv.z + bv.z;
    o.w = (xv.w - mean) * inv * wv.w + bv.w;
    ((float4*)(out + (size_t)row * DD))[t] = o;
}

// ---------------- RoPE on packed QKV (stride 3072) ------------------------------
__global__ void rope_kernel(float* __restrict__ QKV,
                            const float* __restrict__ cosT, const float* __restrict__ sinT) {
    const int idx = blockIdx.x * blockDim.x + threadIdx.x;   // B*S*H*32
    const int p = idx & 31;
    const int h = (idx >> 5) & 15;
    const int s = (idx >> 9) & 1023;
    const int b = idx >> 19;
    const float c  = cosT[s * 32 + p];
    const float sn = sinT[s * 32 + p];
    const size_t base = ((size_t)(b * SS + s)) * QKVN + h * HDIM + 2 * p;
    float2 q = *(float2*)(QKV + base);
    float2 k = *(float2*)(QKV + base + DD);
    float2 qo, ko;
    qo.x = q.x * c - q.y * sn;  qo.y = q.x * sn + q.y * c;
    ko.x = k.x * c - k.y * sn;  ko.y = k.x * sn + k.y * c;
    *(float2*)(QKV + base) = qo;
    *(float2*)(QKV + base + DD) = ko;
}

// ================= tf32 mma.sync GEMM ===========================================
// C[M,N](ldc) = epi(A[M,K] @ BT[N,K]^T)    EPI: 0=none, 1=+Res, 2=exact gelu
// 128x128 CTA tile, 8 warps (2x4), warp tile 64x32, k-chunk 16, double buffer.
#define LDK 20

template<int EPI>
__global__ void __launch_bounds__(256, 2)
mma_gemm(const float* __restrict__ A, const float* __restrict__ BT,
         const float* __restrict__ Res, float* __restrict__ C,
         int M, int N, int K, int ldc) {
    __shared__ float As[2][128 * LDK];
    __shared__ float Bs[2][128 * LDK];

    const int tid  = threadIdx.x;
    const int wid  = tid >> 5, lane = tid & 31;
    const int gid  = lane >> 2, tig = lane & 3;
    const int wm   = wid >> 2;      // 0..1
    const int wn   = wid & 3;       // 0..3
    const int bx = blockIdx.x, by = blockIdx.y;

    const float* Ab = A  + (size_t)(by * 128) * K;
    const float* Bb = BT + (size_t)(bx * 128) * K;

    // producer: rows pr, pr+64; k-quad pk
    const int pr = tid >> 2;
    const int pk = (tid & 3) * 4;

    float acc[16][4];
    #pragma unroll
    for (int i = 0; i < 16; i++)
        #pragma unroll
        for (int j = 0; j < 4; j++) acc[i][j] = 0.f;

    // prologue: chunk 0 -> buffer 0
    {
        float4 a0 = *(const float4*)(Ab + (size_t)pr * K + pk);
        float4 a1 = *(const float4*)(Ab + (size_t)(pr + 64) * K + pk);
        float4 b0 = *(const float4*)(Bb + (size_t)pr * K + pk);
        float4 b1 = *(const float4*)(Bb + (size_t)(pr + 64) * K + pk);
        uint4 u;
        u.x=f2tf32(a0.x); u.y=f2tf32(a0.y); u.z=f2tf32(a0.z); u.w=f2tf32(a0.w);
        *(uint4*)&As[0][pr * LDK + pk] = u;
        u.x=f2tf32(a1.x); u.y=f2tf32(a1.y); u.z=f2tf32(a1.z); u.w=f2tf32(a1.w);
        *(uint4*)&As[0][(pr + 64) * LDK + pk] = u;
        u.x=f2tf32(b0.x); u.y=f2tf32(b0.y); u.z=f2tf32(b0.z); u.w=f2tf32(b0.w);
        *(uint4*)&Bs[0][pr * LDK + pk] = u;
        u.x=f2tf32(b1.x); u.y=f2tf32(b1.y); u.z=f2tf32(b1.z); u.w=f2tf32(b1.w);
        *(uint4*)&Bs[0][(pr + 64) * LDK + pk] = u;
    }
    __syncthreads();

    const int nch = K >> 4;
    for (int c = 0; c < nch; c++) {
        const int buf = c & 1;
        float4 na0, na1, nb0, nb1;
        const bool more = (c + 1 < nch);
        if (more) {
            const float* An = Ab + (c + 1) * 16;
            const float* Bn = Bb + (c + 1) * 16;
            na0 = *(const float4*)(An + (size_t)pr * K + pk);
            na1 = *(const float4*)(An + (size_t)(pr + 64) * K + pk);
            nb0 = *(const float4*)(Bn + (size_t)pr * K + pk);
            nb1 = *(const float4*)(Bn + (size_t)(pr + 64) * K + pk);
        }

        const uint32_t* Asb = (const uint32_t*)As[buf];
        const uint32_t* Bsb = (const uint32_t*)Bs[buf];
        #pragma unroll
        for (int ks = 0; ks < 2; ks++) {
            const int k0 = ks * 8;
            uint32_t bfr[4][2];
            #pragma unroll
            for (int nt = 0; nt < 4; nt++) {
                const uint32_t* p = Bsb + (wn * 32 + nt * 8 + gid) * LDK + k0 + tig;
                bfr[nt][0] = p[0];
                bfr[nt][1] = p[4];
            }
            uint32_t afr[4][4];
            #pragma unroll
            for (int mt = 0; mt < 4; mt++) {
                const uint32_t* p = Asb + (wm * 64 + mt * 16 + gid) * LDK + k0 + tig;
                afr[mt][0] = p[0];
                afr[mt][1] = p[8 * LDK];
                afr[mt][2] = p[4];
                afr[mt][3] = p[8 * LDK + 4];
            }
            #pragma unroll
            for (int mt = 0; mt < 4; mt++)
                #pragma unroll
                for (int nt = 0; nt < 4; nt++)
                    mma16n8k8(acc[mt * 4 + nt], afr[mt], bfr[nt]);
        }

        if (more) {
            const int nb = buf ^ 1;
            uint4 u;
            u.x=f2tf32(na0.x); u.y=f2tf32(na0.y); u.z=f2tf32(na0.z); u.w=f2tf32(na0.w);
            *(uint4*)&As[nb][pr * LDK + pk] = u;
            u.x=f2tf32(na1.x); u.y=f2tf32(na1.y); u.z=f2tf32(na1.z); u.w=f2tf32(na1.w);
            *(uint4*)&As[nb][(pr + 64) * LDK + pk] = u;
            u.x=f2tf32(nb0.x); u.y=f2tf32(nb0.y); u.z=f2tf32(nb0.z); u.w=f2tf32(nb0.w);
            *(uint4*)&Bs[nb][pr * LDK + pk] = u;
            u.x=f2tf32(nb1.x); u.y=f2tf32(nb1.y); u.z=f2tf32(nb1.z); u.w=f2tf32(nb1.w);
            *(uint4*)&Bs[nb][(pr + 64) * LDK + pk] = u;
        }
        __syncthreads();
    }

    // epilogue
    #pragma unroll
    for (int mt = 0; mt < 4; mt++) {
        #pragma unroll
        for (int nt = 0; nt < 4; nt++) {
            const int row = by * 128 + wm * 64 + mt * 16 + gid;
            const int col = bx * 128 + wn * 32 + nt * 8 + tig * 2;
            float v0 = acc[mt*4+nt][0], v1 = acc[mt*4+nt][1];
            float v2 = acc[mt*4+nt][2], v3 = acc[mt*4+nt][3];
            if (EPI == 1) {
                const float2 r0 = *(const float2*)(Res + (size_t)row * ldc + col);
                const float2 r1 = *(const float2*)(Res + (size_t)(row + 8) * ldc + col);
                v0 += r0.x; v1 += r0.y; v2 += r1.x; v3 += r1.y;
            }
            if (EPI == 2) {
                v0 = 0.5f * v0 * (1.0f + erff(v0 * 0.70710678118654752f));
                v1 = 0.5f * v1 * (1.0f + erff(v1 * 0.70710678118654752f));
                v2 = 0.5f * v2 * (1.0f + erff(v2 * 0.70710678118654752f));
                v3 = 0.5f * v3 * (1.0f + erff(v3 * 0.70710678118654752f));
            }
            float2 o0 = {v0, v1}, o1 = {v2, v3};
            *(float2*)(C + (size_t)row * ldc + col) = o0;
            *(float2*)(C + (size_t)(row + 8) * ldc + col) = o1;
        }
    }
}

// ---------------- Flash attention (reads packed QKV, stride 3072) ---------------
#define PADW 68
__global__ void __launch_bounds__(256, 2)
attn_kernel(const float* __restrict__ QKVg, const float* __restrict__ biasg,
            float* __restrict__ Og) {
    extern __shared__ float sm[];
    float* QsT = sm;
    float* KP  = sm + 64 * PADW;
    float* Vs  = sm + 2 * 64 * PADW;

    const int tid = threadIdx.x;
    const int tx = tid & 15, ty = tid >> 4;
    const int qt = blockIdx.x, h = blockIdx.y, b = blockIdx.z;
    const int row0 = qt * 64;

    {
        const int r = tid >> 2;
        const int g = (tid & 3) * 16;
        const float* qp = QKVg + ((size_t)(b * SS + row0 + r)) * QKVN + h * HDIM + g;
        #pragma unroll
        for (int ii = 0; ii < 4; ii++) {
            float4 v = *(const float4*)(qp + ii * 4);
            const int d = g + ii * 4;
            QsT[(d + 0) * PADW + r] = v.x;
            QsT[(d + 1) * PADW + r] = v.y;
            QsT[(d + 2) * PADW + r] = v.z;
            QsT[(d + 3) * PADW + r] = v.w;
        }
    }

    float m_i[4], l_i[4], o_acc[4][4];
    #pragma unroll
    for (int i = 0; i < 4; i++) {
        m_i[i] = -1e30f; l_i[i] = 0.f;
        #pragma unroll
        for (int j = 0; j < 4; j++) o_acc[i][j] = 0.f;
    }
    const float* biasb = biasg + b * SS;

    for (int kt = 0; kt < 16; kt++) {
        __syncthreads();
        {
            const int r = tid >> 2;
            const int g = (tid & 3) * 16;
            const float* kp = QKVg + ((size_t)(b * SS + kt * 64 + r)) * QKVN + DD + h * HDIM + g;
            #pragma unroll
            for (int ii = 0; ii < 4; ii++) {
                float4 v = *(const float4*)(kp + ii * 4);
                const int d = g + ii * 4;
                KP[(d + 0) * PADW + r] = v.x;
                KP[(d + 1) * PADW + r] = v.y;
                KP[(d + 2) * PADW + r] = v.z;
                KP[(d + 3) * PADW + r] = v.w;
            }
            const float* vp = QKVg + ((size_t)(b * SS + kt * 64 + r)) * QKVN + 2 * DD + h * HDIM + g;
            #pragma unroll
            for (int ii = 0; ii < 4; ii++)
                *(float4*)(&Vs[r * PADW + g + ii * 4]) = *(const float4*)(vp + ii * 4);
        }
        __syncthreads();

        float s[4][4];
        #pragma unroll
        for (int i = 0; i < 4; i++)
            #pragma unroll
            for (int j = 0; j < 4; j++) s[i][j] = 0.f;
        #pragma unroll 8
        for (int d = 0; d < 64; d++) {
            float4 a  = *(float4*)(&QsT[d * PADW + ty * 4]);
            float4 kb = *(float4*)(&KP [d * PADW + tx * 4]);
            const float ar[4] = {a.x, a.y, a.z, a.w};
            const float kr[4] = {kb.x, kb.y, kb.z, kb.w};
            #pragma unroll
            for (int i = 0; i < 4; i++)
                #pragma unroll
                for (int j = 0; j < 4; j++)
                    s[i][j] = fmaf(ar[i], kr[j], s[i][j]);
        }
        const float4 bk = *(const float4*)(biasb + kt * 64 + tx * 4);
        const float bias[4] = {bk.x, bk.y, bk.z, bk.w};
        #pragma unroll
        for (int i = 0; i < 4; i++)
            #pragma unroll
            for (int j = 0; j < 4; j++)
                s[i][j] = s[i][j] * 0.125f + bias[j];

        #pragma unroll
        for (int i = 0; i < 4; i++) {
            float mt = fmaxf(fmaxf(s[i][0], s[i][1]), fmaxf(s[i][2], s[i][3]));
            mt = fmaxf(mt, __shfl_xor_sync(0xffffffffu, mt, 1));
            mt = fmaxf(mt, __shfl_xor_sync(0xffffffffu, mt, 2));
            mt = fmaxf(mt, __shfl_xor_sync(0xffffffffu, mt, 4));
            mt = fmaxf(mt, __shfl_xor_sync(0xffffffffu, mt, 8));
            const float mn = fmaxf(m_i[i], mt);
            const float corr = __expf(m_i[i] - mn);
            m_i[i] = mn;
            l_i[i] *= corr;
            #pragma unroll
            for (int j = 0; j < 4; j++) o_acc[i][j] *= corr;
            float ps = 0.f;
            #pragma unroll
            for (int j = 0; j < 4; j++) { s[i][j] = __expf(s[i][j] - mn); ps += s[i][j]; }
            ps += __shfl_xor_sync(0xffffffffu, ps, 1);
            ps += __shfl_xor_sync(0xffffffffu, ps, 2);
            ps += __shfl_xor_sync(0xffffffffu, ps, 4);
            ps += __shfl_xor_sync(0xffffffffu, ps, 8);
            l_i[i] += ps;
        }

        __syncthreads();
        #pragma unroll
        for (int i = 0; i < 4; i++)
            #pragma unroll
            for (int j = 0; j < 4; j++)
                KP[(tx * 4 + j) * PADW + ty * 4 + i] = s[i][j];
        __syncthreads();

        #pragma unroll 8
        for (int kk = 0; kk < 64; kk++) {
            float4 a  = *(float4*)(&KP[kk * PADW + ty * 4]);
            float4 vv = *(float4*)(&Vs[kk * PADW + tx * 4]);
            const float ar[4] = {a.x, a.y, a.z, a.w};
            const float vr[4] = {vv.x, vv.y, vv.z, vv.w};
            #pragma unroll
            for (int i = 0; i < 4; i++)
                #pragma unroll
                for (int j = 0; j < 4; j++)
                    o_acc[i][j] = fmaf(ar[i], vr[j], o_acc[i][j]);
        }
    }

    #pragma unroll
    for (int i = 0; i < 4; i++) {
        const float inv = 1.0f / l_i[i];
        const size_t row = (size_t)(b * SS + row0 + ty * 4 + i);
        float4 o = {o_acc[i][0] * inv, o_acc[i][1] * inv, o_acc[i][2] * inv, o_acc[i][3] * inv};
        *(float4*)(Og + row * DD + h * HDIM + tx * 4) = o;
    }
}

// -------------------------------- launch ---------------------------------------
extern "C" void kernel_launch(void* const* d_in, const int* in_sizes, int n_in,
                              void* d_out, int out_size) {
    const float* x    = (const float*)d_in[0];
    const void*  mask = d_in[1];
    const float* fcos = (const float*)d_in[2];
    const float* fsin = (const float*)d_in[3];
    const float* wq   = (const float*)d_in[4];
    const float* wk   = (const float*)d_in[5];
    const float* wv   = (const float*)d_in[6];
    const float* wo   = (const float*)d_in[7];
    const float* w1   = (const float*)d_in[8];
    const float* w2   = (const float*)d_in[9];
    const float* ln1w = (const float*)d_in[10];
    const float* ln1b = (const float*)d_in[11];
    const float* ln2w = (const float*)d_in[12];
    const float* ln2b = (const float*)d_in[13];
    float* out = (float*)d_out;

    float *H1, *QKV, *ATT, *X1, *G, *BIAS, *WQKVT, *WOT, *W1T, *W2T;
    cudaGetSymbolAddress((void**)&H1,    g_H1);
    cudaGetSymbolAddress((void**)&QKV,   g_QKV);
    cudaGetSymbolAddress((void**)&ATT,   g_ATT);
    cudaGetSymbolAddress((void**)&X1,    g_X1);
    cudaGetSymbolAddress((void**)&G,     g_G);
    cudaGetSymbolAddress((void**)&BIAS,  g_bias);
    cudaGetSymbolAddress((void**)&WQKVT, g_WQKVT);
    cudaGetSymbolAddress((void**)&WOT,   g_WOT);
    cudaGetSymbolAddress((void**)&W1T,   g_W1T);
    cudaGetSymbolAddress((void**)&W2T,   g_W2T);

    static bool attr_set = false;
    if (!attr_set) {
        cudaFuncSetAttribute(attn_kernel, cudaFuncAttributeMaxDynamicSharedMemorySize,
                             3 * 64 * PADW * (int)sizeof(float));
        attr_set = true;
    }

    // 0. mask conversion + weight transposes (QKV weights concatenated)
    mask_detect_kernel<<<1, 256>>>((const unsigned char*)mask);
    mask_convert_kernel<<<NROWS / 256, 256>>>(mask);
    dim3 tb(32, 8);
    transpose_kernel<<<dim3(DD/32, DD/32),  tb>>>(wq, WQKVT,                DD, DD);
    transpose_kernel<<<dim3(DD/32, DD/32),  tb>>>(wk, WQKVT + DD*DD,        DD, DD);
    transpose_kernel<<<dim3(DD/32, DD/32),  tb>>>(wv, WQKVT + 2*DD*DD,      DD, DD);
    transpose_kernel<<<dim3(DD/32, DD/32),  tb>>>(wo, WOT, DD, DD);
    transpose_kernel<<<dim3(FFD/32, DD/32), tb>>>(w1, W1T, DD, FFD);
    transpose_kernel<<<dim3(DD/32, FFD/32), tb>>>(w2, W2T, FFD, DD);

    // 1. h = LN1(x)
    ln_kernel<<<NROWS, 256>>>(x, ln1w, ln1b, H1);
    // 2. QKV = h @ [wq|wk|wv]  (tf32 mma.sync)
    mma_gemm<0><<<dim3(QKVN/128, NROWS/128), 256>>>(H1, WQKVT, nullptr, QKV, NROWS, QKVN, DD, QKVN);
    // 3. RoPE (in packed QKV)
    rope_kernel<<<(BB * SS * HH * 32) / 256, 256>>>(QKV, fcos, fsin);
    // 4. attention
    attn_kernel<<<dim3(SS / 64, HH, BB), 256, 3 * 64 * PADW * sizeof(float)>>>(QKV, BIAS, ATT);
    // 5. X1 = x + ATT @ wo
    mma_gemm<1><<<dim3(DD/128, NROWS/128), 256>>>(ATT, WOT, x, X1, NROWS, DD, DD, DD);
    // 6. h2 = LN2(X1)
    ln_kernel<<<NROWS, 256>>>(X1, ln2w, ln2b, H1);
    // 7. G = gelu(h2 @ w1)
    mma_gemm<2><<<dim3(FFD/128, NROWS/128), 256>>>(H1, W1T, nullptr, G, NROWS, FFD, DD, FFD);
    // 8. out = X1 + G @ w2
    mma_gemm<1><<<dim3(DD/128, NROWS/128), 256>>>(G, W2T, X1, out, NROWS, DD, FFD, DD);
}

// round 6
// speedup vs baseline: 2.0381x; 1.0941x over previous
#include <cuda_runtime.h>
#include <math.h>
#include <stdint.h>

#define BB 4
#define SS 1024
#define DD 1024
#define HH 16
#define HDIM 64
#define FFD 4096
#define NROWS (BB*SS)   // 4096
#define QKVN 3072

// ---------------- scratch (static device globals; allocation-free) -------------
__device__ float g_H1 [NROWS*DD];
__device__ float g_QKV[NROWS*QKVN];   // packed Q|K|V per row
__device__ float g_ATT[NROWS*DD];
__device__ float g_X1 [NROWS*DD];
__device__ float g_G  [NROWS*FFD];
__device__ float g_bias[NROWS];
__device__ int   g_mask_mode;
// transposed weights ([N][K], K-major rows), pre-rounded to tf32 values
__device__ float g_WQKVT[QKVN*DD];
__device__ float g_WOT[DD*DD];
__device__ float g_W1T[FFD*DD];
__device__ float g_W2T[DD*FFD];

__device__ __forceinline__ uint32_t f2tf32(float x) {
    uint32_t u; asm("cvt.rna.tf32.f32 %0, %1;" : "=r"(u) : "f"(x)); return u;
}
__device__ __forceinline__ float roundtf32(float x) {
    return __uint_as_float(f2tf32(x));
}
__device__ __forceinline__ void mma16n8k8(float* d, const uint32_t* a, const uint32_t* b) {
    asm volatile("mma.sync.aligned.m16n8k8.row.col.f32.tf32.tf32.f32 "
        "{%0,%1,%2,%3}, {%4,%5,%6,%7}, {%8,%9}, {%0,%1,%2,%3};"
        : "+f"(d[0]), "+f"(d[1]), "+f"(d[2]), "+f"(d[3])
        : "r"(a[0]), "r"(a[1]), "r"(a[2]), "r"(a[3]), "r"(b[0]), "r"(b[1]));
}
#define CP_ASYNC16(dst, src) \
    asm volatile("cp.async.cg.shared.global [%0], [%1], 16;" :: "r"(dst), "l"(src))
#define CP_COMMIT() asm volatile("cp.async.commit_group;" ::: "memory")
#define CP_WAIT0()  asm volatile("cp.async.wait_group 0;" ::: "memory")

// ---------------- mask dtype sniffing -----------------------------------------
__global__ void mask_detect_kernel(const unsigned char* __restrict__ m) {
    __shared__ int f1, f23;
    if (threadIdx.x == 0) { f1 = 0; f23 = 0; }
    __syncthreads();
    int l1 = 0, l23 = 0;
    for (int i = threadIdx.x; i < NROWS; i += 256) {
        if (m[i]) {
            const int r = i & 3;
            if (r == 1) l1 = 1;
            else if (r >= 2) l23 = 1;
        }
    }
    if (l1)  atomicOr(&f1, 1);
    if (l23) atomicOr(&f23, 1);
    __syncthreads();
    if (threadIdx.x == 0)
        g_mask_mode = f1 ? 1 : (f23 ? 2 : 0);
}
__global__ void mask_convert_kernel(const void* __restrict__ m) {
    const int i = blockIdx.x * blockDim.x + threadIdx.x;
    if (i >= NROWS) return;
    const int mode = g_mask_mode;
    bool t;
    if (mode == 1)      t = ((const unsigned char*)m)[i] != 0;
    else if (mode == 2) t = ((const float*)m)[i] != 0.0f;
    else                t = ((const int*)m)[i] != 0;
    g_bias[i] = t ? -1e30f : 0.0f;
}

// ---------------- weight transpose + tf32 rounding ------------------------------
__global__ void transpose_kernel(const float* __restrict__ in, float* __restrict__ out,
                                 int R, int Ccols) {
    __shared__ float t[32][33];
    const int c0 = blockIdx.x * 32, r0 = blockIdx.y * 32;
    const int x = threadIdx.x, y = threadIdx.y;
    #pragma unroll
    for (int i = 0; i < 32; i += 8)
        t[y + i][x] = in[(size_t)(r0 + y + i) * Ccols + c0 + x];
    __syncthreads();
    #pragma unroll
    for (int i = 0; i < 32; i += 8)
        out[(size_t)(c0 + y + i) * R + r0 + x] = roundtf32(t[x][y + i]);
}

// ---------------- LayerNorm (output rounded to tf32) ----------------------------
__global__ void ln_kernel(const float* __restrict__ x, const float* __restrict__ w,
                          const float* __restrict__ b, float* __restrict__ out) {
    const int row = blockIdx.x;
    const int t = threadIdx.x;
    const float4* xr = (const float4*)(x + (size_t)row * DD);
    float4 xv = xr[t];
    float s  = xv.x + xv.y + xv.z + xv.w;
    float s2 = xv.x*xv.x + xv.y*xv.y + xv.z*xv.z + xv.w*xv.w;
    #pragma unroll
    for (int m = 16; m; m >>= 1) {
        s  += __shfl_xor_sync(0xffffffffu, s,  m);
        s2 += __shfl_xor_sync(0xffffffffu, s2, m);
    }
    __shared__ float ss[8], ss2[8];
    if ((t & 31) == 0) { ss[t >> 5] = s; ss2[t >> 5] = s2; }
    __syncthreads();
    s = 0.f; s2 = 0.f;
    #pragma unroll
    for (int i = 0; i < 8; i++) { s += ss[i]; s2 += ss2[i]; }
    const float mean = s * (1.0f / DD);
    const float var  = s2 * (1.0f / DD) - mean * mean;
    const float inv  = rsqrtf(var + 1e-5f);
    float4 wv = ((const float4*)w)[t];
    float4 bv = ((const float4*)b)[t];
    float4 o;
    o.x = roundtf32((xv.x - mean) * inv * wv.x + bv.x);
    o.y = roundtf32((xv.y - mean) * inv * wv.y + bv.y);
    o.z = roundtf32((xv.z - mean) * inv * wv.z + bv.z);
    o.w = roundtf32((xv.w - mean) * inv * wv.w + bv.w);
    ((float4*)(out + (size_t)row * DD))[t] = o;
}

// ---------------- RoPE on packed QKV (stride 3072) ------------------------------
__global__ void rope_kernel(float* __restrict__ QKV,
                            const float* __restrict__ cosT, const float* __restrict__ sinT) {
    const int idx = blockIdx.x * blockDim.x + threadIdx.x;   // B*S*H*32
    const int p = idx & 31;
    const int h = (idx >> 5) & 15;
    const int s = (idx >> 9) & 1023;
    const int b = idx >> 19;
    const float c  = cosT[s * 32 + p];
    const float sn = sinT[s * 32 + p];
    const size_t base = ((size_t)(b * SS + s)) * QKVN + h * HDIM + 2 * p;
    float2 q = *(float2*)(QKV + base);
    float2 k = *(float2*)(QKV + base + DD);
    float2 qo, ko;
    qo.x = q.x * c - q.y * sn;  qo.y = q.x * sn + q.y * c;
    ko.x = k.x * c - k.y * sn;  ko.y = k.x * sn + k.y * c;
    *(float2*)(QKV + base) = qo;
    *(float2*)(QKV + base + DD) = ko;
}

// ================= tf32 mma.sync GEMM with cp.async pipeline ====================
// C[M,N](ldc) = epi(A[M,K] @ BT[N,K]^T)    EPI: 0=none, 1=+Res, 2=exact gelu->tf32
// A and BT must already hold tf32-rounded values.
// 128x128 CTA tile, 8 warps (2x4), warp tile 64x32, k-chunk 16, double buffer.
#define LDK 20

template<int EPI>
__global__ void __launch_bounds__(256, 2)
mma_gemm(const float* __restrict__ A, const float* __restrict__ BT,
         const float* __restrict__ Res, float* __restrict__ C,
         int M, int N, int K, int ldc) {
    __shared__ float As[2][128 * LDK];
    __shared__ float Bs[2][128 * LDK];

    const int tid  = threadIdx.x;
    const int wid  = tid >> 5, lane = tid & 31;
    const int gid  = lane >> 2, tig = lane & 3;
    const int wm   = wid >> 2;      // 0..1
    const int wn   = wid & 3;       // 0..3
    const int bx = blockIdx.x, by = blockIdx.y;

    const float* Ab = A  + (size_t)(by * 128) * K;
    const float* Bb = BT + (size_t)(bx * 128) * K;

    // producer: rows pr, pr+64; k-quad pk (16B aligned)
    const int pr = tid >> 2;
    const int pk = (tid & 3) * 4;

    const uint32_t sa0 = (uint32_t)__cvta_generic_to_shared(&As[0][pr * LDK + pk]);
    const uint32_t sa0b = (uint32_t)__cvta_generic_to_shared(&As[0][(pr + 64) * LDK + pk]);
    const uint32_t sb0 = (uint32_t)__cvta_generic_to_shared(&Bs[0][pr * LDK + pk]);
    const uint32_t sb0b = (uint32_t)__cvta_generic_to_shared(&Bs[0][(pr + 64) * LDK + pk]);
    const uint32_t bufstride = 128 * LDK * 4;

    float acc[16][4];
    #pragma unroll
    for (int i = 0; i < 16; i++)
        #pragma unroll
        for (int j = 0; j < 4; j++) acc[i][j] = 0.f;

    // prologue: issue chunk 0 into buffer 0
    {
        const float* Ap = Ab + (size_t)pr * K + pk;
        const float* Bp = Bb + (size_t)pr * K + pk;
        CP_ASYNC16(sa0,  Ap);
        CP_ASYNC16(sa0b, Ap + (size_t)64 * K);
        CP_ASYNC16(sb0,  Bp);
        CP_ASYNC16(sb0b, Bp + (size_t)64 * K);
        CP_COMMIT();
    }

    const int nch = K >> 4;
    for (int c = 0; c < nch; c++) {
        CP_WAIT0();
        __syncthreads();

        if (c + 1 < nch) {
            const uint32_t off = ((c + 1) & 1) * bufstride;
            const float* Ap = Ab + (size_t)pr * K + (c + 1) * 16 + pk;
            const float* Bp = Bb + (size_t)pr * K + (c + 1) * 16 + pk;
            CP_ASYNC16(sa0 + off,  Ap);
            CP_ASYNC16(sa0b + off, Ap + (size_t)64 * K);
            CP_ASYNC16(sb0 + off,  Bp);
            CP_ASYNC16(sb0b + off, Bp + (size_t)64 * K);
            CP_COMMIT();
        }

        const int buf = c & 1;
        const uint32_t* Asb = (const uint32_t*)As[buf];
        const uint32_t* Bsb = (const uint32_t*)Bs[buf];
        #pragma unroll
        for (int ks = 0; ks < 2; ks++) {
            const int k0 = ks * 8;
            uint32_t bfr[4][2];
            #pragma unroll
            for (int nt = 0; nt < 4; nt++) {
                const uint32_t* p = Bsb + (wn * 32 + nt * 8 + gid) * LDK + k0 + tig;
                bfr[nt][0] = p[0];
                bfr[nt][1] = p[4];
            }
            uint32_t afr[4][4];
            #pragma unroll
            for (int mt = 0; mt < 4; mt++) {
                const uint32_t* p = Asb + (wm * 64 + mt * 16 + gid) * LDK + k0 + tig;
                afr[mt][0] = p[0];
                afr[mt][1] = p[8 * LDK];
                afr[mt][2] = p[4];
                afr[mt][3] = p[8 * LDK + 4];
            }
            #pragma unroll
            for (int mt = 0; mt < 4; mt++)
                #pragma unroll
                for (int nt = 0; nt < 4; nt++)
                    mma16n8k8(acc[mt * 4 + nt], afr[mt], bfr[nt]);
        }
    }

    // epilogue
    #pragma unroll
    for (int mt = 0; mt < 4; mt++) {
        #pragma unroll
        for (int nt = 0; nt < 4; nt++) {
            const int row = by * 128 + wm * 64 + mt * 16 + gid;
            const int col = bx * 128 + wn * 32 + nt * 8 + tig * 2;
            float v0 = acc[mt*4+nt][0], v1 = acc[mt*4+nt][1];
            float v2 = acc[mt*4+nt][2], v3 = acc[mt*4+nt][3];
            if (EPI == 1) {
                const float2 r0 = *(const float2*)(Res + (size_t)row * ldc + col);
                const float2 r1 = *(const float2*)(Res + (size_t)(row + 8) * ldc + col);
                v0 += r0.x; v1 += r0.y; v2 += r1.x; v3 += r1.y;
            }
            if (EPI == 2) {
                v0 = roundtf32(0.5f * v0 * (1.0f + erff(v0 * 0.70710678118654752f)));
                v1 = roundtf32(0.5f * v1 * (1.0f + erff(v1 * 0.70710678118654752f)));
                v2 = roundtf32(0.5f * v2 * (1.0f + erff(v2 * 0.70710678118654752f)));
                v3 = roundtf32(0.5f * v3 * (1.0f + erff(v3 * 0.70710678118654752f)));
            }
            float2 o0 = {v0, v1}, o1 = {v2, v3};
            *(float2*)(C + (size_t)row * ldc + col) = o0;
            *(float2*)(C + (size_t)(row + 8) * ldc + col) = o1;
        }
    }
}

// ---------------- Flash attention (reads packed QKV; output tf32-rounded) -------
#define PADW 68
__global__ void __launch_bounds__(256, 2)
attn_kernel(const float* __restrict__ QKVg, const float* __restrict__ biasg,
            float* __restrict__ Og) {
    extern __shared__ float sm[];
    float* QsT = sm;
    float* KP  = sm + 64 * PADW;
    float* Vs  = sm + 2 * 64 * PADW;

    const int tid = threadIdx.x;
    const int tx = tid & 15, ty = tid >> 4;
    const int qt = blockIdx.x, h = blockIdx.y, b = blockIdx.z;
    const int row0 = qt * 64;

    {
        const int r = tid >> 2;
        const int g = (tid & 3) * 16;
        const float* qp = QKVg + ((size_t)(b * SS + row0 + r)) * QKVN + h * HDIM + g;
        #pragma unroll
        for (int ii = 0; ii < 4; ii++) {
            float4 v = *(const float4*)(qp + ii * 4);
            const int d = g + ii * 4;
            QsT[(d + 0) * PADW + r] = v.x;
            QsT[(d + 1) * PADW + r] = v.y;
            QsT[(d + 2) * PADW + r] = v.z;
            QsT[(d + 3) * PADW + r] = v.w;
        }
    }

    float m_i[4], l_i[4], o_acc[4][4];
    #pragma unroll
    for (int i = 0; i < 4; i++) {
        m_i[i] = -1e30f; l_i[i] = 0.f;
        #pragma unroll
        for (int j = 0; j < 4; j++) o_acc[i][j] = 0.f;
    }
    const float* biasb = biasg + b * SS;

    for (int kt = 0; kt < 16; kt++) {
        __syncthreads();
        {
            const int r = tid >> 2;
            const int g = (tid & 3) * 16;
            const float* kp = QKVg + ((size_t)(b * SS + kt * 64 + r)) * QKVN + DD + h * HDIM + g;
            #pragma unroll
            for (int ii = 0; ii < 4; ii++) {
                float4 v = *(const float4*)(kp + ii * 4);
                const int d = g + ii * 4;
                KP[(d + 0) * PADW + r] = v.x;
                KP[(d + 1) * PADW + r] = v.y;
                KP[(d + 2) * PADW + r] = v.z;
                KP[(d + 3) * PADW + r] = v.w;
            }
            const float* vp = QKVg + ((size_t)(b * SS + kt * 64 + r)) * QKVN + 2 * DD + h * HDIM + g;
            #pragma unroll
            for (int ii = 0; ii < 4; ii++)
                *(float4*)(&Vs[r * PADW + g + ii * 4]) = *(const float4*)(vp + ii * 4);
        }
        __syncthreads();

        float s[4][4];
        #pragma unroll
        for (int i = 0; i < 4; i++)
            #pragma unroll
            for (int j = 0; j < 4; j++) s[i][j] = 0.f;
        #pragma unroll 8
        for (int d = 0; d < 64; d++) {
            float4 a  = *(float4*)(&QsT[d * PADW + ty * 4]);
            float4 kb = *(float4*)(&KP [d * PADW + tx * 4]);
            const float ar[4] = {a.x, a.y, a.z, a.w};
            const float kr[4] = {kb.x, kb.y, kb.z, kb.w};
            #pragma unroll
            for (int i = 0; i < 4; i++)
                #pragma unroll
                for (int j = 0; j < 4; j++)
                    s[i][j] = fmaf(ar[i], kr[j], s[i][j]);
        }
        const float4 bk = *(const float4*)(biasb + kt * 64 + tx * 4);
        const float bias[4] = {bk.x, bk.y, bk.z, bk.w};
        #pragma unroll
        for (int i = 0; i < 4; i++)
            #pragma unroll
            for (int j = 0; j < 4; j++)
                s[i][j] = s[i][j] * 0.125f + bias[j];

        #pragma unroll
        for (int i = 0; i < 4; i++) {
            float mt = fmaxf(fmaxf(s[i][0], s[i][1]), fmaxf(s[i][2], s[i][3]));
            mt = fmaxf(mt, __shfl_xor_sync(0xffffffffu, mt, 1));
            mt = fmaxf(mt, __shfl_xor_sync(0xffffffffu, mt, 2));
            mt = fmaxf(mt, __shfl_xor_sync(0xffffffffu, mt, 4));
            mt = fmaxf(mt, __shfl_xor_sync(0xffffffffu, mt, 8));
            const float mn = fmaxf(m_i[i], mt);
            const float corr = __expf(m_i[i] - mn);
            m_i[i] = mn;
            l_i[i] *= corr;
            #pragma unroll
            for (int j = 0; j < 4; j++) o_acc[i][j] *= corr;
            float ps = 0.f;
            #pragma unroll
            for (int j = 0; j < 4; j++) { s[i][j] = __expf(s[i][j] - mn); ps += s[i][j]; }
            ps += __shfl_xor_sync(0xffffffffu, ps, 1);
            ps += __shfl_xor_sync(0xffffffffu, ps, 2);
            ps += __shfl_xor_sync(0xffffffffu, ps, 4);
            ps += __shfl_xor_sync(0xffffffffu, ps, 8);
            l_i[i] += ps;
        }

        __syncthreads();
        #pragma unroll
        for (int i = 0; i < 4; i++)
            #pragma unroll
            for (int j = 0; j < 4; j++)
                KP[(tx * 4 + j) * PADW + ty * 4 + i] = s[i][j];
        __syncthreads();

        #pragma unroll 8
        for (int kk = 0; kk < 64; kk++) {
            float4 a  = *(float4*)(&KP[kk * PADW + ty * 4]);
            float4 vv = *(float4*)(&Vs[kk * PADW + tx * 4]);
            const float ar[4] = {a.x, a.y, a.z, a.w};
            const float vr[4] = {vv.x, vv.y, vv.z, vv.w};
            #pragma unroll
            for (int i = 0; i < 4; i++)
                #pragma unroll
                for (int j = 0; j < 4; j++)
                    o_acc[i][j] = fmaf(ar[i], vr[j], o_acc[i][j]);
        }
    }

    #pragma unroll
    for (int i = 0; i < 4; i++) {
        const float inv = 1.0f / l_i[i];
        const size_t row = (size_t)(b * SS + row0 + ty * 4 + i);
        float4 o = {roundtf32(o_acc[i][0] * inv), roundtf32(o_acc[i][1] * inv),
                    roundtf32(o_acc[i][2] * inv), roundtf32(o_acc[i][3] * inv)};
        *(float4*)(Og + row * DD + h * HDIM + tx * 4) = o;
    }
}

// -------------------------------- launch ---------------------------------------
extern "C" void kernel_launch(void* const* d_in, const int* in_sizes, int n_in,
                              void* d_out, int out_size) {
    const float* x    = (const float*)d_in[0];
    const void*  mask = d_in[1];
    const float* fcos = (const float*)d_in[2];
    const float* fsin = (const float*)d_in[3];
    const float* wq   = (const float*)d_in[4];
    const float* wk   = (const float*)d_in[5];
    const float* wv   = (const float*)d_in[6];
    const float* wo   = (const float*)d_in[7];
    const float* w1   = (const float*)d_in[8];
    const float* w2   = (const float*)d_in[9];
    const float* ln1w = (const float*)d_in[10];
    const float* ln1b = (const float*)d_in[11];
    const float* ln2w = (const float*)d_in[12];
    const float* ln2b = (const float*)d_in[13];
    float* out = (float*)d_out;

    float *H1, *QKV, *ATT, *X1, *G, *BIAS, *WQKVT, *WOT, *W1T, *W2T;
    cudaGetSymbolAddress((void**)&H1,    g_H1);
    cudaGetSymbolAddress((void**)&QKV,   g_QKV);
    cudaGetSymbolAddress((void**)&ATT,   g_ATT);
    cudaGetSymbolAddress((void**)&X1,    g_X1);
    cudaGetSymbolAddress((void**)&G,     g_G);
    cudaGetSymbolAddress((void**)&BIAS,  g_bias);
    cudaGetSymbolAddress((void**)&WQKVT, g_WQKVT);
    cudaGetSymbolAddress((void**)&WOT,   g_WOT);
    cudaGetSymbolAddress((void**)&W1T,   g_W1T);
    cudaGetSymbolAddress((void**)&W2T,   g_W2T);

    static bool attr_set = false;
    if (!attr_set) {
        cudaFuncSetAttribute(attn_kernel, cudaFuncAttributeMaxDynamicSharedMemorySize,
                             3 * 64 * PADW * (int)sizeof(float));
        attr_set = true;
    }

    // 0. mask conversion + weight transposes (tf32-rounded, QKV concatenated)
    mask_detect_kernel<<<1, 256>>>((const unsigned char*)mask);
    mask_convert_kernel<<<NROWS / 256, 256>>>(mask);
    dim3 tb(32, 8);
    transpose_kernel<<<dim3(DD/32, DD/32),  tb>>>(wq, WQKVT,                DD, DD);
    transpose_kernel<<<dim3(DD/32, DD/32),  tb>>>(wk, WQKVT + DD*DD,        DD, DD);
    transpose_kernel<<<dim3(DD/32, DD/32),  tb>>>(wv, WQKVT + 2*DD*DD,      DD, DD);
    transpose_kernel<<<dim3(DD/32, DD/32),  tb>>>(wo, WOT, DD, DD);
    transpose_kernel<<<dim3(FFD/32, DD/32), tb>>>(w1, W1T, DD, FFD);
    transpose_kernel<<<dim3(DD/32, FFD/32), tb>>>(w2, W2T, FFD, DD);

    // 1. h = LN1(x)  (tf32-rounded output)
    ln_kernel<<<NROWS, 256>>>(x, ln1w, ln1b, H1);
    // 2. QKV = h @ [wq|wk|wv]  (tf32 mma.sync + cp.async)
    mma_gemm<0><<<dim3(QKVN/128, NROWS/128), 256>>>(H1, WQKVT, nullptr, QKV, NROWS, QKVN, DD, QKVN);
    // 3. RoPE (in packed QKV)
    rope_kernel<<<(BB * SS * HH * 32) / 256, 256>>>(QKV, fcos, fsin);
    // 4. attention
    attn_kernel<<<dim3(SS / 64, HH, BB), 256, 3 * 64 * PADW * sizeof(float)>>>(QKV, BIAS, ATT);
    // 5. X1 = x + ATT @ wo
    mma_gemm<1><<<dim3(DD/128, NROWS/128), 256>>>(ATT, WOT, x, X1, NROWS, DD, DD, DD);
    // 6. h2 = LN2(X1)  (tf32-rounded output)
    ln_kernel<<<NROWS, 256>>>(X1, ln2w, ln2b, H1);
    // 7. G = gelu(h2 @ w1)  (tf32-rounded output)
    mma_gemm<2><<<dim3(FFD/128, NROWS/128), 256>>>(H1, W1T, nullptr, G, NROWS, FFD, DD, FFD);
    // 8. out = X1 + G @ w2
    mma_gemm<1><<<dim3(DD/128, NROWS/128), 256>>>(G, W2T, X1, out, NROWS, DD, FFD, DD);
}

// round 8
// speedup vs baseline: 2.1924x; 1.0757x over previous
#include <cuda_runtime.h>
#include <math.h>
#include <stdint.h>

#define BB 4
#define SS 1024
#define DD 1024
#define HH 16
#define HDIM 64
#define FFD 4096
#define NROWS (BB*SS)   // 4096
#define QKVN 3072

// ---------------- scratch (static device globals; allocation-free) -------------
__device__ float g_H1 [NROWS*DD];
__device__ float g_QKV[NROWS*QKVN];   // packed Q|K|V per row
__device__ float g_ATT[NROWS*DD];
__device__ float g_X1 [NROWS*DD];
__device__ float g_G  [NROWS*FFD];
__device__ float g_bias[NROWS];
__device__ int   g_mask_mode;
// transposed weights ([N][K], K-major rows), pre-rounded to tf32 values
__device__ float g_WQKVT[QKVN*DD];
__device__ float g_WOT[DD*DD];
__device__ float g_W1T[FFD*DD];
__device__ float g_W2T[DD*FFD];

__device__ __forceinline__ uint32_t f2tf32(float x) {
    uint32_t u; asm("cvt.rna.tf32.f32 %0, %1;" : "=r"(u) : "f"(x)); return u;
}
__device__ __forceinline__ float roundtf32(float x) {
    return __uint_as_float(f2tf32(x));
}
__device__ __forceinline__ void mma16n8k8(float* d, const uint32_t* a, const uint32_t* b) {
    asm volatile("mma.sync.aligned.m16n8k8.row.col.f32.tf32.tf32.f32 "
        "{%0,%1,%2,%3}, {%4,%5,%6,%7}, {%8,%9}, {%0,%1,%2,%3};"
        : "+f"(d[0]), "+f"(d[1]), "+f"(d[2]), "+f"(d[3])
        : "r"(a[0]), "r"(a[1]), "r"(a[2]), "r"(a[3]), "r"(b[0]), "r"(b[1]));
}
#define LDSM4(r0, r1, r2, r3, addr) \
    asm volatile("ldmatrix.sync.aligned.m8n8.x4.shared.b16 {%0,%1,%2,%3}, [%4];" \
        : "=r"(r0), "=r"(r1), "=r"(r2), "=r"(r3) : "r"(addr))
#define CP_ASYNC16(dst, src) \
    asm volatile("cp.async.cg.shared.global [%0], [%1], 16;" :: "r"(dst), "l"(src))
#define CP_COMMIT() asm volatile("cp.async.commit_group;" ::: "memory")
#define CP_WAIT0()  asm volatile("cp.async.wait_group 0;" ::: "memory")
#define CP_WAIT1()  asm volatile("cp.async.wait_group 1;" ::: "memory")

// ---------------- mask dtype sniffing -----------------------------------------
__global__ void mask_detect_kernel(const unsigned char* __restrict__ m) {
    __shared__ int f1, f23;
    if (threadIdx.x == 0) { f1 = 0; f23 = 0; }
    __syncthreads();
    int l1 = 0, l23 = 0;
    for (int i = threadIdx.x; i < NROWS; i += 256) {
        if (m[i]) {
            const int r = i & 3;
            if (r == 1) l1 = 1;
            else if (r >= 2) l23 = 1;
        }
    }
    if (l1)  atomicOr(&f1, 1);
    if (l23) atomicOr(&f23, 1);
    __syncthreads();
    if (threadIdx.x == 0)
        g_mask_mode = f1 ? 1 : (f23 ? 2 : 0);
}
__global__ void mask_convert_kernel(const void* __restrict__ m) {
    const int i = blockIdx.x * blockDim.x + threadIdx.x;
    if (i >= NROWS) return;
    const int mode = g_mask_mode;
    bool t;
    if (mode == 1)      t = ((const unsigned char*)m)[i] != 0;
    else if (mode == 2) t = ((const float*)m)[i] != 0.0f;
    else                t = ((const int*)m)[i] != 0;
    g_bias[i] = t ? -1e30f : 0.0f;
}

// ---------------- weight transpose + tf32 rounding ------------------------------
__global__ void transpose_kernel(const float* __restrict__ in, float* __restrict__ out,
                                 int R, int Ccols) {
    __shared__ float t[32][33];
    const int c0 = blockIdx.x * 32, r0 = blockIdx.y * 32;
    const int x = threadIdx.x, y = threadIdx.y;
    #pragma unroll
    for (int i = 0; i < 32; i += 8)
        t[y + i][x] = in[(size_t)(r0 + y + i) * Ccols + c0 + x];
    __syncthreads();
    #pragma unroll
    for (int i = 0; i < 32; i += 8)
        out[(size_t)(c0 + y + i) * R + r0 + x] = roundtf32(t[x][y + i]);
}

// ---------------- LayerNorm (output rounded to tf32) ----------------------------
__global__ void ln_kernel(const float* __restrict__ x, const float* __restrict__ w,
                          const float* __restrict__ b, float* __restrict__ out) {
    const int row = blockIdx.x;
    const int t = threadIdx.x;
    const float4* xr = (const float4*)(x + (size_t)row * DD);
    float4 xv = xr[t];
    float s  = xv.x + xv.y + xv.z + xv.w;
    float s2 = xv.x*xv.x + xv.y*xv.y + xv.z*xv.z + xv.w*xv.w;
    #pragma unroll
    for (int m = 16; m; m >>= 1) {
        s  += __shfl_xor_sync(0xffffffffu, s,  m);
        s2 += __shfl_xor_sync(0xffffffffu, s2, m);
    }
    __shared__ float ss[8], ss2[8];
    if ((t & 31) == 0) { ss[t >> 5] = s; ss2[t >> 5] = s2; }
    __syncthreads();
    s = 0.f; s2 = 0.f;
    #pragma unroll
    for (int i = 0; i < 8; i++) { s += ss[i]; s2 += ss2[i]; }
    const float mean = s * (1.0f / DD);
    const float var  = s2 * (1.0f / DD) - mean * mean;
    const float inv  = rsqrtf(var + 1e-5f);
    float4 wv = ((const float4*)w)[t];
    float4 bv = ((const float4*)b)[t];
    float4 o;
    o.x = roundtf32((xv.x - mean) * inv * wv.x + bv.x);
    o.y = roundtf32((xv.y - mean) * inv * wv.y + bv.y);
    o.z = roundtf32((xv.z - mean) * inv * wv.z + bv.z);
    o.w = roundtf32((xv.w - mean) * inv * wv.w + bv.w);
    ((float4*)(out + (size_t)row * DD))[t] = o;
}

// ---------------- RoPE on packed QKV (stride 3072) ------------------------------
__global__ void rope_kernel(float* __restrict__ QKV,
                            const float* __restrict__ cosT, const float* __restrict__ sinT) {
    const int idx = blockIdx.x * blockDim.x + threadIdx.x;   // B*S*H*32
    const int p = idx & 31;
    const int h = (idx >> 5) & 15;
    const int s = (idx >> 9) & 1023;
    const int b = idx >> 19;
    const float c  = cosT[s * 32 + p];
    const float sn = sinT[s * 32 + p];
    const size_t base = ((size_t)(b * SS + s)) * QKVN + h * HDIM + 2 * p;
    float2 q = *(float2*)(QKV + base);
    float2 k = *(float2*)(QKV + base + DD);
    float2 qo, ko;
    qo.x = q.x * c - q.y * sn;  qo.y = q.x * sn + q.y * c;
    ko.x = k.x * c - k.y * sn;  ko.y = k.x * sn + k.y * c;
    *(float2*)(QKV + base) = qo;
    *(float2*)(QKV + base + DD) = ko;
}

// ================= tf32 mma.sync GEMM: ldmatrix + 3-stage cp.async ==============
// C[M,N](ldc) = epi(A[M,K] @ BT[N,K]^T)    EPI: 0=none, 1=+Res, 2=exact gelu->tf32
// A and BT must already hold tf32-rounded values.
// 128x128 CTA tile, 8 warps (2x4), warp tile 64x32, k-chunk 16, 3-stage pipeline.
#define LDK 20
#define STAGE_BYTES (128 * LDK * 4)            // 10240 B per operand per stage
#define GEMM_SMEM   (6 * STAGE_BYTES)          // 3 stages x (A + B) = 61440 B

template<int EPI>
__global__ void __launch_bounds__(256, 2)
mma_gemm(const float* __restrict__ A, const float* __restrict__ BT,
         const float* __restrict__ Res, float* __restrict__ C,
         int M, int N, int K, int ldc) {
    extern __shared__ float smbuf[];
    const uint32_t sbase = (uint32_t)__cvta_generic_to_shared(smbuf);
    const uint32_t sA = sbase;                       // 3 A stages
    const uint32_t sB = sbase + 3 * STAGE_BYTES;     // 3 B stages

    const int tid  = threadIdx.x;
    const int wid  = tid >> 5, lane = tid & 31;
    const int wm   = wid >> 2;      // 0..1
    const int wn   = wid & 3;       // 0..3
    const int bx = blockIdx.x, by = blockIdx.y;

    const float* Ab = A  + (size_t)(by * 128) * K;
    const float* Bb = BT + (size_t)(bx * 128) * K;

    // producer: rows pr, pr+64; k-quad pk (16B)
    const int pr = tid >> 2;
    const int pk = (tid & 3) * 4;
    const uint32_t pdst  = (uint32_t)((pr * LDK + pk) * 4);
    const uint32_t pdst2 = (uint32_t)(((pr + 64) * LDK + pk) * 4);

    // ldmatrix lane addressing (byte offsets within a stage)
    // A fragment tiles: rows (wm*64 + mt*16 + (lane&15)), k half (lane>>4)*4
    const uint32_t aoff = (uint32_t)((((wm * 64) + (lane & 15)) * LDK + ((lane >> 4) << 2)) * 4);
    // B fragment tiles: rows (wn*32 + p*16 + ((lane>>4)<<3) + (lane&7)), k half ((lane>>3)&1)*4
    const uint32_t boff = (uint32_t)((((wn * 32) + ((lane >> 4) << 3) + (lane & 7)) * LDK
                                     + (((lane >> 3) & 1) << 2)) * 4);

    float acc[16][4];
    #pragma unroll
    for (int i = 0; i < 16; i++)
        #pragma unroll
        for (int j = 0; j < 4; j++) acc[i][j] = 0.f;

    const int nch = K >> 4;

    // prologue: issue chunks 0 and 1 into stages 0 and 1
    #pragma unroll
    for (int c0 = 0; c0 < 2; c0++) {
        const uint32_t so = (uint32_t)(c0 * STAGE_BYTES);
        const float* Ap = Ab + (size_t)pr * K + c0 * 16 + pk;
        const float* Bp = Bb + (size_t)pr * K + c0 * 16 + pk;
        CP_ASYNC16(sA + so + pdst,  Ap);
        CP_ASYNC16(sA + so + pdst2, Ap + (size_t)64 * K);
        CP_ASYNC16(sB + so + pdst,  Bp);
        CP_ASYNC16(sB + so + pdst2, Bp + (size_t)64 * K);
        CP_COMMIT();
    }

    int stage = 0;
    for (int c = 0; c < nch; c++) {
        if (c + 1 < nch) { CP_WAIT1(); } else { CP_WAIT0(); }
        __syncthreads();

        if (c + 2 < nch) {
            int ns = stage + 2; if (ns >= 3) ns -= 3;
            const uint32_t so = (uint32_t)(ns * STAGE_BYTES);
            const float* Ap = Ab + (size_t)pr * K + (c + 2) * 16 + pk;
            const float* Bp = Bb + (size_t)pr * K + (c + 2) * 16 + pk;
            CP_ASYNC16(sA + so + pdst,  Ap);
            CP_ASYNC16(sA + so + pdst2, Ap + (size_t)64 * K);
            CP_ASYNC16(sB + so + pdst,  Bp);
            CP_ASYNC16(sB + so + pdst2, Bp + (size_t)64 * K);
            CP_COMMIT();
        }

        const uint32_t aSt = sA + (uint32_t)(stage * STAGE_BYTES);
        const uint32_t bSt = sB + (uint32_t)(stage * STAGE_BYTES);
        #pragma unroll
        for (int ks = 0; ks < 2; ks++) {
            const uint32_t k0b = (uint32_t)(ks * 8 * 4);
            uint32_t bfr[4][2];
            #pragma unroll
            for (int p = 0; p < 2; p++) {
                uint32_t r0, r1, r2, r3;
                LDSM4(r0, r1, r2, r3, bSt + boff + k0b + (uint32_t)(p * 16 * LDK * 4));
                bfr[2*p][0] = r0; bfr[2*p][1] = r1;
                bfr[2*p+1][0] = r2; bfr[2*p+1][1] = r3;
            }
            uint32_t afr[4][4];
            #pragma unroll
            for (int mt = 0; mt < 4; mt++) {
                LDSM4(afr[mt][0], afr[mt][1], afr[mt][2], afr[mt][3],
                      aSt + aoff + k0b + (uint32_t)(mt * 16 * LDK * 4));
            }
            #pragma unroll
            for (int mt = 0; mt < 4; mt++)
                #pragma unroll
                for (int nt = 0; nt < 4; nt++)
                    mma16n8k8(acc[mt * 4 + nt], afr[mt], bfr[nt]);
        }
        stage++; if (stage >= 3) stage = 0;
    }

    // epilogue
    const int gid = lane >> 2, tig = lane & 3;
    #pragma unroll
    for (int mt = 0; mt < 4; mt++) {
        #pragma unroll
        for (int nt = 0; nt < 4; nt++) {
            const int row = by * 128 + wm * 64 + mt * 16 + gid;
            const int col = bx * 128 + wn * 32 + nt * 8 + tig * 2;
            float v0 = acc[mt*4+nt][0], v1 = acc[mt*4+nt][1];
            float v2 = acc[mt*4+nt][2], v3 = acc[mt*4+nt][3];
            if (EPI == 1) {
                const float2 r0 = *(const float2*)(Res + (size_t)row * ldc + col);
                const float2 r1 = *(const float2*)(Res + (size_t)(row + 8) * ldc + col);
                v0 += r0.x; v1 += r0.y; v2 += r1.x; v3 += r1.y;
            }
            if (EPI == 2) {
                v0 = roundtf32(0.5f * v0 * (1.0f + erff(v0 * 0.70710678118654752f)));
                v1 = roundtf32(0.5f * v1 * (1.0f + erff(v1 * 0.70710678118654752f)));
                v2 = roundtf32(0.5f * v2 * (1.0f + erff(v2 * 0.70710678118654752f)));
                v3 = roundtf32(0.5f * v3 * (1.0f + erff(v3 * 0.70710678118654752f)));
            }
            float2 o0 = {v0, v1}, o1 = {v2, v3};
            *(float2*)(C + (size_t)row * ldc + col) = o0;
            *(float2*)(C + (size_t)(row + 8) * ldc + col) = o1;
        }
    }
}

// ---------------- Flash attention (reads packed QKV; output tf32-rounded) -------
#define PADW 68
__global__ void __launch_bounds__(256, 2)
attn_kernel(const float* __restrict__ QKVg, const float* __restrict__ biasg,
            float* __restrict__ Og) {
    extern __shared__ float sm[];
    float* QsT = sm;
    float* KP  = sm + 64 * PADW;
    float* Vs  = sm + 2 * 64 * PADW;

    const int tid = threadIdx.x;
    const int tx = tid & 15, ty = tid >> 4;
    const int qt = blockIdx.x, h = blockIdx.y, b = blockIdx.z;
    const int row0 = qt * 64;

    {
        const int r = tid >> 2;
        const int g = (tid & 3) * 16;
        const float* qp = QKVg + ((size_t)(b * SS + row0 + r)) * QKVN + h * HDIM + g;
        #pragma unroll
        for (int ii = 0; ii < 4; ii++) {
            float4 v = *(const float4*)(qp + ii * 4);
            const int d = g + ii * 4;
            QsT[(d + 0) * PADW + r] = v.x;
            QsT[(d + 1) * PADW + r] = v.y;
            QsT[(d + 2) * PADW + r] = v.z;
            QsT[(d + 3) * PADW + r] = v.w;
        }
    }

    float m_i[4], l_i[4], o_acc[4][4];
    #pragma unroll
    for (int i = 0; i < 4; i++) {
        m_i[i] = -1e30f; l_i[i] = 0.f;
        #pragma unroll
        for (int j = 0; j < 4; j++) o_acc[i][j] = 0.f;
    }
    const float* biasb = biasg + b * SS;

    for (int kt = 0; kt < 16; kt++) {
        __syncthreads();
        {
            const int r = tid >> 2;
            const int g = (tid & 3) * 16;
            const float* kp = QKVg + ((size_t)(b * SS + kt * 64 + r)) * QKVN + DD + h * HDIM + g;
            #pragma unroll
            for (int ii = 0; ii < 4; ii++) {
                float4 v = *(const float4*)(kp + ii * 4);
                const int d = g + ii * 4;
                KP[(d + 0) * PADW + r] = v.x;
                KP[(d + 1) * PADW + r] = v.y;
                KP[(d + 2) * PADW + r] = v.z;
                KP[(d + 3) * PADW + r] = v.w;
            }
            const float* vp = QKVg + ((size_t)(b * SS + kt * 64 + r)) * QKVN + 2 * DD + h * HDIM + g;
            #pragma unroll
            for (int ii = 0; ii < 4; ii++)
                *(float4*)(&Vs[r * PADW + g + ii * 4]) = *(const float4*)(vp + ii * 4);
        }
        __syncthreads();

        float s[4][4];
        #pragma unroll
        for (int i = 0; i < 4; i++)
            #pragma unroll
            for (int j = 0; j < 4; j++) s[i][j] = 0.f;
        #pragma unroll 8
        for (int d = 0; d < 64; d++) {
            float4 a  = *(float4*)(&QsT[d * PADW + ty * 4]);
            float4 kb = *(float4*)(&KP [d * PADW + tx * 4]);
            const float ar[4] = {a.x, a.y, a.z, a.w};
            const float kr[4] = {kb.x, kb.y, kb.z, kb.w};
            #pragma unroll
            for (int i = 0; i < 4; i++)
                #pragma unroll
                for (int j = 0; j < 4; j++)
                    s[i][j] = fmaf(ar[i], kr[j], s[i][j]);
        }
        const float4 bk = *(const float4*)(biasb + kt * 64 + tx * 4);
        const float bias[4] = {bk.x, bk.y, bk.z, bk.w};
        #pragma unroll
        for (int i = 0; i < 4; i++)
            #pragma unroll
            for (int j = 0; j < 4; j++)
                s[i][j] = s[i][j] * 0.125f + bias[j];

        #pragma unroll
        for (int i = 0; i < 4; i++) {
            float mt = fmaxf(fmaxf(s[i][0], s[i][1]), fmaxf(s[i][2], s[i][3]));
            mt = fmaxf(mt, __shfl_xor_sync(0xffffffffu, mt, 1));
            mt = fmaxf(mt, __shfl_xor_sync(0xffffffffu, mt, 2));
            mt = fmaxf(mt, __shfl_xor_sync(0xffffffffu, mt, 4));
            mt = fmaxf(mt, __shfl_xor_sync(0xffffffffu, mt, 8));
            const float mn = fmaxf(m_i[i], mt);
            const float corr = __expf(m_i[i] - mn);
            m_i[i] = mn;
            l_i[i] *= corr;
            #pragma unroll
            for (int j = 0; j < 4; j++) o_acc[i][j] *= corr;
            float ps = 0.f;
            #pragma unroll
            for (int j = 0; j < 4; j++) { s[i][j] = __expf(s[i][j] - mn); ps += s[i][j]; }
            ps += __shfl_xor_sync(0xffffffffu, ps, 1);
            ps += __shfl_xor_sync(0xffffffffu, ps, 2);
            ps += __shfl_xor_sync(0xffffffffu, ps, 4);
            ps += __shfl_xor_sync(0xffffffffu, ps, 8);
            l_i[i] += ps;
        }

        __syncthreads();
        #pragma unroll
        for (int i = 0; i < 4; i++)
            #pragma unroll
            for (int j = 0; j < 4; j++)
                KP[(tx * 4 + j) * PADW + ty * 4 + i] = s[i][j];
        __syncthreads();

        #pragma unroll 8
        for (int kk = 0; kk < 64; kk++) {
            float4 a  = *(float4*)(&KP[kk * PADW + ty * 4]);
            float4 vv = *(float4*)(&Vs[kk * PADW + tx * 4]);
            const float ar[4] = {a.x, a.y, a.z, a.w};
            const float vr[4] = {vv.x, vv.y, vv.z, vv.w};
            #pragma unroll
            for (int i = 0; i < 4; i++)
                #pragma unroll
                for (int j = 0; j < 4; j++)
                    o_acc[i][j] = fmaf(ar[i], vr[j], o_acc[i][j]);
        }
    }

    #pragma unroll
    for (int i = 0; i < 4; i++) {
        const float inv = 1.0f / l_i[i];
        const size_t row = (size_t)(b * SS + row0 + ty * 4 + i);
        float4 o = {roundtf32(o_acc[i][0] * inv), roundtf32(o_acc[i][1] * inv),
                    roundtf32(o_acc[i][2] * inv), roundtf32(o_acc[i][3] * inv)};
        *(float4*)(Og + row * DD + h * HDIM + tx * 4) = o;
    }
}

// -------------------------------- launch ---------------------------------------
extern "C" void kernel_launch(void* const* d_in, const int* in_sizes, int n_in,
                              void* d_out, int out_size) {
    const float* x    = (const float*)d_in[0];
    const void*  mask = d_in[1];
    const float* fcos = (const float*)d_in[2];
    const float* fsin = (const float*)d_in[3];
    const float* wq   = (const float*)d_in[4];
    const float* wk   = (const float*)d_in[5];
    const float* wv   = (const float*)d_in[6];
    const float* wo   = (const float*)d_in[7];
    const float* w1   = (const float*)d_in[8];
    const float* w2   = (const float*)d_in[9];
    const float* ln1w = (const float*)d_in[10];
    const float* ln1b = (const float*)d_in[11];
    const float* ln2w = (const float*)d_in[12];
    const float* ln2b = (const float*)d_in[13];
    float* out = (float*)d_out;

    float *H1, *QKV, *ATT, *X1, *G, *BIAS, *WQKVT, *WOT, *W1T, *W2T;
    cudaGetSymbolAddress((void**)&H1,    g_H1);
    cudaGetSymbolAddress((void**)&QKV,   g_QKV);
    cudaGetSymbolAddress((void**)&ATT,   g_ATT);
    cudaGetSymbolAddress((void**)&X1,    g_X1);
    cudaGetSymbolAddress((void**)&G,     g_G);
    cudaGetSymbolAddress((void**)&BIAS,  g_bias);
    cudaGetSymbolAddress((void**)&WQKVT, g_WQKVT);
    cudaGetSymbolAddress((void**)&WOT,   g_WOT);
    cudaGetSymbolAddress((void**)&W1T,   g_W1T);
    cudaGetSymbolAddress((void**)&W2T,   g_W2T);

    static bool attr_set = false;
    if (!attr_set) {
        cudaFuncSetAttribute(attn_kernel, cudaFuncAttributeMaxDynamicSharedMemorySize,
                             3 * 64 * PADW * (int)sizeof(float));
        cudaFuncSetAttribute(mma_gemm<0>, cudaFuncAttributeMaxDynamicSharedMemorySize, GEMM_SMEM);
        cudaFuncSetAttribute(mma_gemm<1>, cudaFuncAttributeMaxDynamicSharedMemorySize, GEMM_SMEM);
        cudaFuncSetAttribute(mma_gemm<2>, cudaFuncAttributeMaxDynamicSharedMemorySize, GEMM_SMEM);
        attr_set = true;
    }

    // 0. mask conversion + weight transposes (tf32-rounded, QKV concatenated)
    mask_detect_kernel<<<1, 256>>>((const unsigned char*)mask);
    mask_convert_kernel<<<NROWS / 256, 256>>>(mask);
    dim3 tb(32, 8);
    transpose_kernel<<<dim3(DD/32, DD/32),  tb>>>(wq, WQKVT,                DD, DD);
    transpose_kernel<<<dim3(DD/32, DD/32),  tb>>>(wk, WQKVT + DD*DD,        DD, DD);
    transpose_kernel<<<dim3(DD/32, DD/32),  tb>>>(wv, WQKVT + 2*DD*DD,      DD, DD);
    transpose_kernel<<<dim3(DD/32, DD/32),  tb>>>(wo, WOT, DD, DD);
    transpose_kernel<<<dim3(FFD/32, DD/32), tb>>>(w1, W1T, DD, FFD);
    transpose_kernel<<<dim3(DD/32, FFD/32), tb>>>(w2, W2T, FFD, DD);

    // 1. h = LN1(x)  (tf32-rounded output)
    ln_kernel<<<NROWS, 256>>>(x, ln1w, ln1b, H1);
    // 2. QKV = h @ [wq|wk|wv]
    mma_gemm<0><<<dim3(QKVN/128, NROWS/128), 256, GEMM_SMEM>>>(H1, WQKVT, nullptr, QKV, NROWS, QKVN, DD, QKVN);
    // 3. RoPE (in packed QKV)
    rope_kernel<<<(BB * SS * HH * 32) / 256, 256>>>(QKV, fcos, fsin);
    // 4. attention
    attn_kernel<<<dim3(SS / 64, HH, BB), 256, 3 * 64 * PADW * sizeof(float)>>>(QKV, BIAS, ATT);
    // 5. X1 = x + ATT @ wo
    mma_gemm<1><<<dim3(DD/128, NROWS/128), 256, GEMM_SMEM>>>(ATT, WOT, x, X1, NROWS, DD, DD, DD);
    // 6. h2 = LN2(X1)  (tf32-rounded output)
    ln_kernel<<<NROWS, 256>>>(X1, ln2w, ln2b, H1);
    // 7. G = gelu(h2 @ w1)  (tf32-rounded output)
    mma_gemm<2><<<dim3(FFD/128, NROWS/128), 256, GEMM_SMEM>>>(H1, W1T, nullptr, G, NROWS, FFD, DD, FFD);
    // 8. out = X1 + G @ w2
    mma_gemm<1><<<dim3(DD/128, NROWS/128), 256, GEMM_SMEM>>>(G, W2T, X1, out, NROWS, DD, FFD, DD);
}

// round 9
// speedup vs baseline: 2.8176x; 1.2852x over previous
#include <cuda_runtime.h>
#include <cuda_fp16.h>
#include <math.h>
#include <stdint.h>

#define BB 4
#define SS 1024
#define DD 1024
#define HH 16
#define HDIM 64
#define FFD 4096
#define NROWS (BB*SS)   // 4096
#define QKVN 3072

// ---------------- scratch (static device globals; allocation-free) -------------
__device__ __half g_H1 [NROWS*DD];
__device__ float  g_QKV[NROWS*QKVN];   // packed Q|K|V per row (fp32)
__device__ __half g_ATT[NROWS*DD];
__device__ float  g_X1 [NROWS*DD];
__device__ __half g_G  [NROWS*FFD];
__device__ float  g_bias[NROWS];
__device__ int    g_mask_mode;
// transposed weights ([N][K], K-major rows), fp16
__device__ __half g_WQKVT[QKVN*DD];
__device__ __half g_WOT[DD*DD];
__device__ __half g_W1T[FFD*DD];
__device__ __half g_W2T[DD*FFD];

__device__ __forceinline__ void mma16n8k16(float* d, const uint32_t* a, const uint32_t* b) {
    asm volatile("mma.sync.aligned.m16n8k16.row.col.f32.f16.f16.f32 "
        "{%0,%1,%2,%3}, {%4,%5,%6,%7}, {%8,%9}, {%0,%1,%2,%3};"
        : "+f"(d[0]), "+f"(d[1]), "+f"(d[2]), "+f"(d[3])
        : "r"(a[0]), "r"(a[1]), "r"(a[2]), "r"(a[3]), "r"(b[0]), "r"(b[1]));
}
#define LDSM4(r0, r1, r2, r3, addr) \
    asm volatile("ldmatrix.sync.aligned.m8n8.x4.shared.b16 {%0,%1,%2,%3}, [%4];" \
        : "=r"(r0), "=r"(r1), "=r"(r2), "=r"(r3) : "r"(addr))
#define CP_ASYNC16(dst, src) \
    asm volatile("cp.async.cg.shared.global [%0], [%1], 16;" :: "r"(dst), "l"(src))
#define CP_COMMIT() asm volatile("cp.async.commit_group;" ::: "memory")
#define CP_WAIT0()  asm volatile("cp.async.wait_group 0;" ::: "memory")
#define CP_WAIT1()  asm volatile("cp.async.wait_group 1;" ::: "memory")

// ---------------- mask dtype sniffing -----------------------------------------
__global__ void mask_detect_kernel(const unsigned char* __restrict__ m) {
    __shared__ int f1, f23;
    if (threadIdx.x == 0) { f1 = 0; f23 = 0; }
    __syncthreads();
    int l1 = 0, l23 = 0;
    for (int i = threadIdx.x; i < NROWS; i += 256) {
        if (m[i]) {
            const int r = i & 3;
            if (r == 1) l1 = 1;
            else if (r >= 2) l23 = 1;
        }
    }
    if (l1)  atomicOr(&f1, 1);
    if (l23) atomicOr(&f23, 1);
    __syncthreads();
    if (threadIdx.x == 0)
        g_mask_mode = f1 ? 1 : (f23 ? 2 : 0);
}
__global__ void mask_convert_kernel(const void* __restrict__ m) {
    const int i = blockIdx.x * blockDim.x + threadIdx.x;
    if (i >= NROWS) return;
    const int mode = g_mask_mode;
    bool t;
    if (mode == 1)      t = ((const unsigned char*)m)[i] != 0;
    else if (mode == 2) t = ((const float*)m)[i] != 0.0f;
    else                t = ((const int*)m)[i] != 0;
    g_bias[i] = t ? -1e30f : 0.0f;
}

// ---------------- weight transpose + fp16 conversion ----------------------------
__global__ void transpose_kernel(const float* __restrict__ in, __half* __restrict__ out,
                                 int R, int Ccols) {
    __shared__ float t[32][33];
    const int c0 = blockIdx.x * 32, r0 = blockIdx.y * 32;
    const int x = threadIdx.x, y = threadIdx.y;
    #pragma unroll
    for (int i = 0; i < 32; i += 8)
        t[y + i][x] = in[(size_t)(r0 + y + i) * Ccols + c0 + x];
    __syncthreads();
    #pragma unroll
    for (int i = 0; i < 32; i += 8)
        out[(size_t)(c0 + y + i) * R + r0 + x] = __float2half_rn(t[x][y + i]);
}

// ---------------- LayerNorm (fp16 output) ---------------------------------------
__global__ void ln_kernel(const float* __restrict__ x, const float* __restrict__ w,
                          const float* __restrict__ b, __half* __restrict__ out) {
    const int row = blockIdx.x;
    const int t = threadIdx.x;
    const float4* xr = (const float4*)(x + (size_t)row * DD);
    float4 xv = xr[t];
    float s  = xv.x + xv.y + xv.z + xv.w;
    float s2 = xv.x*xv.x + xv.y*xv.y + xv.z*xv.z + xv.w*xv.w;
    #pragma unroll
    for (int m = 16; m; m >>= 1) {
        s  += __shfl_xor_sync(0xffffffffu, s,  m);
        s2 += __shfl_xor_sync(0xffffffffu, s2, m);
    }
    __shared__ float ss[8], ss2[8];
    if ((t & 31) == 0) { ss[t >> 5] = s; ss2[t >> 5] = s2; }
    __syncthreads();
    s = 0.f; s2 = 0.f;
    #pragma unroll
    for (int i = 0; i < 8; i++) { s += ss[i]; s2 += ss2[i]; }
    const float mean = s * (1.0f / DD);
    const float var  = s2 * (1.0f / DD) - mean * mean;
    const float inv  = rsqrtf(var + 1e-5f);
    float4 wv = ((const float4*)w)[t];
    float4 bv = ((const float4*)b)[t];
    __half2 h0 = __floats2half2_rn((xv.x - mean) * inv * wv.x + bv.x,
                                   (xv.y - mean) * inv * wv.y + bv.y);
    __half2 h1 = __floats2half2_rn((xv.z - mean) * inv * wv.z + bv.z,
                                   (xv.w - mean) * inv * wv.w + bv.w);
    uint2 o = {*(uint32_t*)&h0, *(uint32_t*)&h1};
    *(uint2*)(out + (size_t)row * DD + t * 4) = o;
}

// ---------------- RoPE on packed QKV (stride 3072, fp32) ------------------------
__global__ void rope_kernel(float* __restrict__ QKV,
                            const float* __restrict__ cosT, const float* __restrict__ sinT) {
    const int idx = blockIdx.x * blockDim.x + threadIdx.x;   // B*S*H*32
    const int p = idx & 31;
    const int h = (idx >> 5) & 15;
    const int s = (idx >> 9) & 1023;
    const int b = idx >> 19;
    const float c  = cosT[s * 32 + p];
    const float sn = sinT[s * 32 + p];
    const size_t base = ((size_t)(b * SS + s)) * QKVN + h * HDIM + 2 * p;
    float2 q = *(float2*)(QKV + base);
    float2 k = *(float2*)(QKV + base + DD);
    float2 qo, ko;
    qo.x = q.x * c - q.y * sn;  qo.y = q.x * sn + q.y * c;
    ko.x = k.x * c - k.y * sn;  ko.y = k.x * sn + k.y * c;
    *(float2*)(QKV + base) = qo;
    *(float2*)(QKV + base + DD) = ko;
}

// ================= fp16 mma.sync GEMM: ldmatrix + 3-stage cp.async ==============
// C[M,N](ldc) = epi(A[M,K] @ BT[N,K]^T),  A/BT fp16, accum fp32.
// EPI: 0=fp32 out, 1=fp32 out +Res, 2=gelu -> fp16 out
// 128x128 CTA tile, 8 warps (2x4), warp tile 64x32, k-chunk 32, 3-stage pipeline.
#define LDKH 40
#define STAGE_BYTES (128 * LDKH * 2)           // 10240 B per operand per stage
#define GEMM_SMEM   (6 * STAGE_BYTES)          // 61440 B

template<int EPI>
__global__ void __launch_bounds__(256, 2)
mma_gemm(const __half* __restrict__ A, const __half* __restrict__ BT,
         const float* __restrict__ Res, void* __restrict__ Cout,
         int M, int N, int K, int ldc) {
    extern __shared__ __half smbuf[];
    const uint32_t sbase = (uint32_t)__cvta_generic_to_shared(smbuf);
    const uint32_t sA = sbase;                       // 3 A stages
    const uint32_t sB = sbase + 3 * STAGE_BYTES;     // 3 B stages

    const int tid  = threadIdx.x;
    const int wid  = tid >> 5, lane = tid & 31;
    const int wm   = wid >> 2;      // 0..1
    const int wn   = wid & 3;       // 0..3
    const int bx = blockIdx.x, by = blockIdx.y;

    const __half* Ab = A  + (size_t)(by * 128) * K;
    const __half* Bb = BT + (size_t)(bx * 128) * K;

    // producer: row pr (0..127), half-offset pkh in {0,16}; 2x 16B cp per operand
    const int pr  = tid >> 1;
    const int pkh = (tid & 1) * 16;
    const uint32_t pdst = (uint32_t)((pr * LDKH + pkh) * 2);

    // ldmatrix lane addressing (byte offsets within a stage)
    // A: rows wm*64 + mt*16 + (lane&15), k-half (lane>>4)*8 halves
    const uint32_t aoff = (uint32_t)((((wm * 64) + (lane & 15)) * LDKH + ((lane >> 4) << 3)) * 2);
    // B: rows wn*32 + p*16 + ((lane>>4)<<3) + (lane&7), k-half ((lane>>3)&1)*8 halves
    const uint32_t boff = (uint32_t)((((wn * 32) + ((lane >> 4) << 3) + (lane & 7)) * LDKH
                                     + (((lane >> 3) & 1) << 3)) * 2);

    float acc[16][4];
    #pragma unroll
    for (int i = 0; i < 16; i++)
        #pragma unroll
        for (int j = 0; j < 4; j++) acc[i][j] = 0.f;

    const int nch = K >> 5;   // k-chunk 32

    // prologue: issue chunks 0 and 1 into stages 0 and 1
    #pragma unroll
    for (int c0 = 0; c0 < 2; c0++) {
        const uint32_t so = (uint32_t)(c0 * STAGE_BYTES);
        const __half* Ap = Ab + (size_t)pr * K + c0 * 32 + pkh;
        const __half* Bp = Bb + (size_t)pr * K + c0 * 32 + pkh;
        CP_ASYNC16(sA + so + pdst,      Ap);
        CP_ASYNC16(sA + so + pdst + 16, Ap + 8);
        CP_ASYNC16(sB + so + pdst,      Bp);
        CP_ASYNC16(sB + so + pdst + 16, Bp + 8);
        CP_COMMIT();
    }

    int stage = 0;
    for (int c = 0; c < nch; c++) {
        if (c + 1 < nch) { CP_WAIT1(); } else { CP_WAIT0(); }
        __syncthreads();

        if (c + 2 < nch) {
            int ns = stage + 2; if (ns >= 3) ns -= 3;
            const uint32_t so = (uint32_t)(ns * STAGE_BYTES);
            const __half* Ap = Ab + (size_t)pr * K + (c + 2) * 32 + pkh;
            const __half* Bp = Bb + (size_t)pr * K + (c + 2) * 32 + pkh;
            CP_ASYNC16(sA + so + pdst,      Ap);
            CP_ASYNC16(sA + so + pdst + 16, Ap + 8);
            CP_ASYNC16(sB + so + pdst,      Bp);
            CP_ASYNC16(sB + so + pdst + 16, Bp + 8);
            CP_COMMIT();
        }

        const uint32_t aSt = sA + (uint32_t)(stage * STAGE_BYTES);
        const uint32_t bSt = sB + (uint32_t)(stage * STAGE_BYTES);
        #pragma unroll
        for (int ks = 0; ks < 2; ks++) {      // two k16 steps per chunk
            const uint32_t k0b = (uint32_t)(ks * 16 * 2);   // 16 halves
            uint32_t bfr[4][2];
            #pragma unroll
            for (int p = 0; p < 2; p++) {
                uint32_t r0, r1, r2, r3;
                LDSM4(r0, r1, r2, r3, bSt + boff + k0b + (uint32_t)(p * 16 * LDKH * 2));
                bfr[2*p][0] = r0; bfr[2*p][1] = r1;
                bfr[2*p+1][0] = r2; bfr[2*p+1][1] = r3;
            }
            uint32_t afr[4][4];
            #pragma unroll
            for (int mt = 0; mt < 4; mt++) {
                LDSM4(afr[mt][0], afr[mt][1], afr[mt][2], afr[mt][3],
                      aSt + aoff + k0b + (uint32_t)(mt * 16 * LDKH * 2));
            }
            #pragma unroll
            for (int mt = 0; mt < 4; mt++)
                #pragma unroll
                for (int nt = 0; nt < 4; nt++)
                    mma16n8k16(acc[mt * 4 + nt], afr[mt], bfr[nt]);
        }
        stage++; if (stage >= 3) stage = 0;
    }

    // epilogue
    const int gid = lane >> 2, tig = lane & 3;
    #pragma unroll
    for (int mt = 0; mt < 4; mt++) {
        #pragma unroll
        for (int nt = 0; nt < 4; nt++) {
            const int row = by * 128 + wm * 64 + mt * 16 + gid;
            const int col = bx * 128 + wn * 32 + nt * 8 + tig * 2;
            float v0 = acc[mt*4+nt][0], v1 = acc[mt*4+nt][1];
            float v2 = acc[mt*4+nt][2], v3 = acc[mt*4+nt][3];
            if (EPI == 1) {
                const float2 r0 = *(const float2*)(Res + (size_t)row * ldc + col);
                const float2 r1 = *(const float2*)(Res + (size_t)(row + 8) * ldc + col);
                v0 += r0.x; v1 += r0.y; v2 += r1.x; v3 += r1.y;
            }
            if (EPI == 2) {
                // gelu -> fp16 output
                v0 = 0.5f * v0 * (1.0f + erff(v0 * 0.70710678118654752f));
                v1 = 0.5f * v1 * (1.0f + erff(v1 * 0.70710678118654752f));
                v2 = 0.5f * v2 * (1.0f + erff(v2 * 0.70710678118654752f));
                v3 = 0.5f * v3 * (1.0f + erff(v3 * 0.70710678118654752f));
                __half* Ch = (__half*)Cout;
                __half2 h0 = __floats2half2_rn(v0, v1);
                __half2 h1 = __floats2half2_rn(v2, v3);
                *(__half2*)(Ch + (size_t)row * ldc + col) = h0;
                *(__half2*)(Ch + (size_t)(row + 8) * ldc + col) = h1;
            } else {
                float* Cf = (float*)Cout;
                float2 o0 = {v0, v1}, o1 = {v2, v3};
                *(float2*)(Cf + (size_t)row * ldc + col) = o0;
                *(float2*)(Cf + (size_t)(row + 8) * ldc + col) = o1;
            }
        }
    }
}

// ---------------- Flash attention (fp32 QKV in, fp16 out) -----------------------
#define PADW 68
__global__ void __launch_bounds__(256, 2)
attn_kernel(const float* __restrict__ QKVg, const float* __restrict__ biasg,
            __half* __restrict__ Og) {
    extern __shared__ float sm[];
    float* QsT = sm;
    float* KP  = sm + 64 * PADW;
    float* Vs  = sm + 2 * 64 * PADW;

    const int tid = threadIdx.x;
    const int tx = tid & 15, ty = tid >> 4;
    const int qt = blockIdx.x, h = blockIdx.y, b = blockIdx.z;
    const int row0 = qt * 64;

    {
        const int r = tid >> 2;
        const int g = (tid & 3) * 16;
        const float* qp = QKVg + ((size_t)(b * SS + row0 + r)) * QKVN + h * HDIM + g;
        #pragma unroll
        for (int ii = 0; ii < 4; ii++) {
            float4 v = *(const float4*)(qp + ii * 4);
            const int d = g + ii * 4;
            QsT[(d + 0) * PADW + r] = v.x;
            QsT[(d + 1) * PADW + r] = v.y;
            QsT[(d + 2) * PADW + r] = v.z;
            QsT[(d + 3) * PADW + r] = v.w;
        }
    }

    float m_i[4], l_i[4], o_acc[4][4];
    #pragma unroll
    for (int i = 0; i < 4; i++) {
        m_i[i] = -1e30f; l_i[i] = 0.f;
        #pragma unroll
        for (int j = 0; j < 4; j++) o_acc[i][j] = 0.f;
    }
    const float* biasb = biasg + b * SS;

    for (int kt = 0; kt < 16; kt++) {
        __syncthreads();
        {
            const int r = tid >> 2;
            const int g = (tid & 3) * 16;
            const float* kp = QKVg + ((size_t)(b * SS + kt * 64 + r)) * QKVN + DD + h * HDIM + g;
            #pragma unroll
            for (int ii = 0; ii < 4; ii++) {
                float4 v = *(const float4*)(kp + ii * 4);
                const int d = g + ii * 4;
                KP[(d + 0) * PADW + r] = v.x;
                KP[(d + 1) * PADW + r] = v.y;
                KP[(d + 2) * PADW + r] = v.z;
                KP[(d + 3) * PADW + r] = v.w;
            }
            const float* vp = QKVg + ((size_t)(b * SS + kt * 64 + r)) * QKVN + 2 * DD + h * HDIM + g;
            #pragma unroll
            for (int ii = 0; ii < 4; ii++)
                *(float4*)(&Vs[r * PADW + g + ii * 4]) = *(const float4*)(vp + ii * 4);
        }
        __syncthreads();

        float s[4][4];
        #pragma unroll
        for (int i = 0; i < 4; i++)
            #pragma unroll
            for (int j = 0; j < 4; j++) s[i][j] = 0.f;
        #pragma unroll 8
        for (int d = 0; d < 64; d++) {
            float4 a  = *(float4*)(&QsT[d * PADW + ty * 4]);
            float4 kb = *(float4*)(&KP [d * PADW + tx * 4]);
            const float ar[4] = {a.x, a.y, a.z, a.w};
            const float kr[4] = {kb.x, kb.y, kb.z, kb.w};
            #pragma unroll
            for (int i = 0; i < 4; i++)
                #pragma unroll
                for (int j = 0; j < 4; j++)
                    s[i][j] = fmaf(ar[i], kr[j], s[i][j]);
        }
        const float4 bk = *(const float4*)(biasb + kt * 64 + tx * 4);
        const float bias[4] = {bk.x, bk.y, bk.z, bk.w};
        #pragma unroll
        for (int i = 0; i < 4; i++)
            #pragma unroll
            for (int j = 0; j < 4; j++)
                s[i][j] = s[i][j] * 0.125f + bias[j];

        #pragma unroll
        for (int i = 0; i < 4; i++) {
            float mt = fmaxf(fmaxf(s[i][0], s[i][1]), fmaxf(s[i][2], s[i][3]));
            mt = fmaxf(mt, __shfl_xor_sync(0xffffffffu, mt, 1));
            mt = fmaxf(mt, __shfl_xor_sync(0xffffffffu, mt, 2));
            mt = fmaxf(mt, __shfl_xor_sync(0xffffffffu, mt, 4));
            mt = fmaxf(mt, __shfl_xor_sync(0xffffffffu, mt, 8));
            const float mn = fmaxf(m_i[i], mt);
            const float corr = __expf(m_i[i] - mn);
            m_i[i] = mn;
            l_i[i] *= corr;
            #pragma unroll
            for (int j = 0; j < 4; j++) o_acc[i][j] *= corr;
            float ps = 0.f;
            #pragma unroll
            for (int j = 0; j < 4; j++) { s[i][j] = __expf(s[i][j] - mn); ps += s[i][j]; }
            ps += __shfl_xor_sync(0xffffffffu, ps, 1);
            ps += __shfl_xor_sync(0xffffffffu, ps, 2);
            ps += __shfl_xor_sync(0xffffffffu, ps, 4);
            ps += __shfl_xor_sync(0xffffffffu, ps, 8);
            l_i[i] += ps;
        }

        __syncthreads();
        #pragma unroll
        for (int i = 0; i < 4; i++)
            #pragma unroll
            for (int j = 0; j < 4; j++)
                KP[(tx * 4 + j) * PADW + ty * 4 + i] = s[i][j];
        __syncthreads();

        #pragma unroll 8
        for (int kk = 0; kk < 64; kk++) {
            float4 a  = *(float4*)(&KP[kk * PADW + ty * 4]);
            float4 vv = *(float4*)(&Vs[kk * PADW + tx * 4]);
            const float ar[4] = {a.x, a.y, a.z, a.w};
            const float vr[4] = {vv.x, vv.y, vv.z, vv.w};
            #pragma unroll
            for (int i = 0; i < 4; i++)
                #pragma unroll
                for (int j = 0; j < 4; j++)
                    o_acc[i][j] = fmaf(ar[i], vr[j], o_acc[i][j]);
        }
    }

    #pragma unroll
    for (int i = 0; i < 4; i++) {
        const float inv = 1.0f / l_i[i];
        const size_t row = (size_t)(b * SS + row0 + ty * 4 + i);
        __half2 h0 = __floats2half2_rn(o_acc[i][0] * inv, o_acc[i][1] * inv);
        __half2 h1 = __floats2half2_rn(o_acc[i][2] * inv, o_acc[i][3] * inv);
        uint2 o = {*(uint32_t*)&h0, *(uint32_t*)&h1};
        *(uint2*)(Og + row * DD + h * HDIM + tx * 4) = o;
    }
}

// -------------------------------- launch ---------------------------------------
extern "C" void kernel_launch(void* const* d_in, const int* in_sizes, int n_in,
                              void* d_out, int out_size) {
    const float* x    = (const float*)d_in[0];
    const void*  mask = d_in[1];
    const float* fcos = (const float*)d_in[2];
    const float* fsin = (const float*)d_in[3];
    const float* wq   = (const float*)d_in[4];
    const float* wk   = (const float*)d_in[5];
    const float* wv   = (const float*)d_in[6];
    const float* wo   = (const float*)d_in[7];
    const float* w1   = (const float*)d_in[8];
    const float* w2   = (const float*)d_in[9];
    const float* ln1w = (const float*)d_in[10];
    const float* ln1b = (const float*)d_in[11];
    const float* ln2w = (const float*)d_in[12];
    const float* ln2b = (const float*)d_in[13];
    float* out = (float*)d_out;

    __half *H1, *ATT, *G, *WQKVT, *WOT, *W1T, *W2T;
    float *QKV, *X1, *BIAS;
    cudaGetSymbolAddress((void**)&H1,    g_H1);
    cudaGetSymbolAddress((void**)&QKV,   g_QKV);
    cudaGetSymbolAddress((void**)&ATT,   g_ATT);
    cudaGetSymbolAddress((void**)&X1,    g_X1);
    cudaGetSymbolAddress((void**)&G,     g_G);
    cudaGetSymbolAddress((void**)&BIAS,  g_bias);
    cudaGetSymbolAddress((void**)&WQKVT, g_WQKVT);
    cudaGetSymbolAddress((void**)&WOT,   g_WOT);
    cudaGetSymbolAddress((void**)&W1T,   g_W1T);
    cudaGetSymbolAddress((void**)&W2T,   g_W2T);

    static bool attr_set = false;
    if (!attr_set) {
        cudaFuncSetAttribute(attn_kernel, cudaFuncAttributeMaxDynamicSharedMemorySize,
                             3 * 64 * PADW * (int)sizeof(float));
        cudaFuncSetAttribute(mma_gemm<0>, cudaFuncAttributeMaxDynamicSharedMemorySize, GEMM_SMEM);
        cudaFuncSetAttribute(mma_gemm<1>, cudaFuncAttributeMaxDynamicSharedMemorySize, GEMM_SMEM);
        cudaFuncSetAttribute(mma_gemm<2>, cudaFuncAttributeMaxDynamicSharedMemorySize, GEMM_SMEM);
        attr_set = true;
    }

    // 0. mask conversion + weight transposes (fp16, QKV concatenated)
    mask_detect_kernel<<<1, 256>>>((const unsigned char*)mask);
    mask_convert_kernel<<<NROWS / 256, 256>>>(mask);
    dim3 tb(32, 8);
    transpose_kernel<<<dim3(DD/32, DD/32),  tb>>>(wq, WQKVT,                DD, DD);
    transpose_kernel<<<dim3(DD/32, DD/32),  tb>>>(wk, WQKVT + DD*DD,        DD, DD);
    transpose_kernel<<<dim3(DD/32, DD/32),  tb>>>(wv, WQKVT + 2*DD*DD,      DD, DD);
    transpose_kernel<<<dim3(DD/32, DD/32),  tb>>>(wo, WOT, DD, DD);
    transpose_kernel<<<dim3(FFD/32, DD/32), tb>>>(w1, W1T, DD, FFD);
    transpose_kernel<<<dim3(DD/32, FFD/32), tb>>>(w2, W2T, FFD, DD);

    // 1. h = LN1(x)  (fp16 output)
    ln_kernel<<<NROWS, 256>>>(x, ln1w, ln1b, H1);
    // 2. QKV = h @ [wq|wk|wv]  (fp16 mma, fp32 out)
    mma_gemm<0><<<dim3(QKVN/128, NROWS/128), 256, GEMM_SMEM>>>(H1, WQKVT, nullptr, QKV, NROWS, QKVN, DD, QKVN);
    // 3. RoPE (in packed fp32 QKV)
    rope_kernel<<<(BB * SS * HH * 32) / 256, 256>>>(QKV, fcos, fsin);
    // 4. attention (fp16 output)
    attn_kernel<<<dim3(SS / 64, HH, BB), 256, 3 * 64 * PADW * sizeof(float)>>>(QKV, BIAS, ATT);
    // 5. X1 = x + ATT @ wo  (fp32 out)
    mma_gemm<1><<<dim3(DD/128, NROWS/128), 256, GEMM_SMEM>>>(ATT, WOT, x, X1, NROWS, DD, DD, DD);
    // 6. h2 = LN2(X1)  (fp16 output)
    ln_kernel<<<NROWS, 256>>>(X1, ln2w, ln2b, H1);
    // 7. G = gelu(h2 @ w1)  (fp16 output)
    mma_gemm<2><<<dim3(FFD/128, NROWS/128), 256, GEMM_SMEM>>>(H1, W1T, nullptr, G, NROWS, FFD, DD, FFD);
    // 8. out = X1 + G @ w2  (fp32 out)
    mma_gemm<1><<<dim3(DD/128, NROWS/128), 256, GEMM_SMEM>>>(G, W2T, X1, out, NROWS, DD, FFD, DD);
}